// round 1
// baseline (speedup 1.0000x reference)
#include <cuda_runtime.h>
#include <cuda_bf16.h>
#include <math.h>

// Problem constants
#define BB 4
#define NN 6
#define FDIM 256
#define DDIM 128
#define HH 64
#define WW 120
#define PP (HH*WW)          // 7680
#define BN (BB*NN)          // 24
#define IMG_H 480.0f
#define IMG_W 960.0f

// Scratch (device globals — no runtime allocation allowed)
__device__ float g_val[(size_t)BN * PP * DDIM];   // (bn, p, d)  94.4 MB
__device__ float g_z[(size_t)BB * PP * DDIM];     // (b, p, d)   15.7 MB
__device__ float g_Hm[BN * 9];
__device__ float g_bnscale[FDIM];
__device__ float g_bnshift[FDIM];

// ---------------------------------------------------------------------------
// K0: homographies + BN scale/shift
// ---------------------------------------------------------------------------
__global__ void k0_prep(const float* __restrict__ I_src,
                        const float* __restrict__ I_tar_inv,
                        const float* __restrict__ E,
                        const float* __restrict__ disp,
                        const float* __restrict__ nvec,
                        const float* __restrict__ bng,
                        const float* __restrict__ bnb,
                        const float* __restrict__ bnm,
                        const float* __restrict__ bnv)
{
    int t = threadIdx.x;
    if (t < FDIM) {
        float sc = bng[t] * rsqrtf(bnv[t] + 1e-5f);
        g_bnscale[t] = sc;
        g_bnshift[t] = bnb[t] - bnm[t] * sc;
    }
    if (t < BN) {
        int b = t / NN;
        float dis = disp[0];
        const float* Eb = E + t * 16;        // (4,4)
        const float* Ks = I_src + t * 9;     // (3,3)
        const float* Kt = I_tar_inv + b * 9; // (3,3)
        float nv0 = nvec[b*3+0], nv1 = nvec[b*3+1], nv2 = nvec[b*3+2];
        float A[9];
        #pragma unroll
        for (int i = 0; i < 3; i++) {
            float Ti = Eb[i*4+3] / dis;
            A[i*3+0] = Eb[i*4+0] - Ti * nv0;
            A[i*3+1] = Eb[i*4+1] - Ti * nv1;
            A[i*3+2] = Eb[i*4+2] - Ti * nv2;
        }
        float M[9];
        #pragma unroll
        for (int i = 0; i < 3; i++)
            #pragma unroll
            for (int j = 0; j < 3; j++)
                M[i*3+j] = Ks[i*3+0]*A[0*3+j] + Ks[i*3+1]*A[1*3+j] + Ks[i*3+2]*A[2*3+j];
        #pragma unroll
        for (int i = 0; i < 3; i++)
            #pragma unroll
            for (int j = 0; j < 3; j++)
                g_Hm[t*9 + i*3+j] = M[i*3+0]*Kt[0*3+j] + M[i*3+1]*Kt[1*3+j] + M[i*3+2]*Kt[2*3+j];
    }
}

// ---------------------------------------------------------------------------
// K1: fused BN+ReLU + GEMM:  val_t[bn][p][d] = sum_f W[d][f] * relu(bn(feat))
// tile: 128 pixels x 128 d, BK=16, 256 threads, 8x8 per thread
// ---------------------------------------------------------------------------
__global__ void __launch_bounds__(256) k1_conv(const float* __restrict__ feat,
                                               const float* __restrict__ Wc)
{
    __shared__ float Fs[16][132]; // [f][p]
    __shared__ float Ws[16][132]; // [f][d]
    int bn = blockIdx.y;
    int p0 = blockIdx.x * 128;
    int t  = threadIdx.x;
    int px_ = t & 15;   // pixel sub-tile
    int py_ = t >> 4;   // d sub-tile

    float acc[8][8];
    #pragma unroll
    for (int i = 0; i < 8; i++)
        #pragma unroll
        for (int j = 0; j < 8; j++) acc[i][j] = 0.f;

    const float* fbase = feat + (size_t)bn * FDIM * PP + p0;

    for (int f0 = 0; f0 < FDIM; f0 += 16) {
        #pragma unroll
        for (int i = 0; i < 8; i++) {
            int idx = t + i * 256;
            int ff = idx >> 7, pp = idx & 127;
            int f = f0 + ff;
            float v = fbase[(size_t)f * PP + pp];
            v = fmaxf(fmaf(v, g_bnscale[f], g_bnshift[f]), 0.f);
            Fs[ff][pp] = v;
        }
        #pragma unroll
        for (int i = 0; i < 8; i++) {
            int idx = t + i * 256;
            int ff = idx & 15, d = idx >> 4;
            Ws[ff][d] = Wc[d * FDIM + f0 + ff];
        }
        __syncthreads();
        #pragma unroll
        for (int kk = 0; kk < 16; kk++) {
            float a[8], b[8];
            #pragma unroll
            for (int j = 0; j < 8; j++) a[j] = Ws[kk][py_*8 + j];
            #pragma unroll
            for (int i = 0; i < 8; i++) b[i] = Fs[kk][px_*8 + i];
            #pragma unroll
            for (int i = 0; i < 8; i++)
                #pragma unroll
                for (int j = 0; j < 8; j++)
                    acc[i][j] = fmaf(b[i], a[j], acc[i][j]);
        }
        __syncthreads();
    }

    float* outp = g_val + ((size_t)bn * PP + p0 + px_*8) * DDIM + py_*8;
    #pragma unroll
    for (int i = 0; i < 8; i++) {
        float4 v0 = make_float4(acc[i][0], acc[i][1], acc[i][2], acc[i][3]);
        float4 v1 = make_float4(acc[i][4], acc[i][5], acc[i][6], acc[i][7]);
        *(float4*)(outp + (size_t)i * DDIM)     = v0;
        *(float4*)(outp + (size_t)i * DDIM + 4) = v1;
    }
}

// ---------------------------------------------------------------------------
// K2: homography + bilinear sample + normalized dot + softmax + weighted sum
// one warp per pixel; 8 pixels per block
// ---------------------------------------------------------------------------
__device__ __forceinline__ float wred(float v) {
    #pragma unroll
    for (int o = 16; o; o >>= 1) v += __shfl_xor_sync(0xffffffffu, v, o);
    return v;
}

__global__ void __launch_bounds__(256) k2_attn()
{
    int b    = blockIdx.y;
    int p    = blockIdx.x * 8 + (threadIdx.x >> 5);
    int lane = threadIdx.x & 31;

    int col = p % WW, row = p / WW;
    float pxc = (float)col * (IMG_W / (float)(WW - 1));
    float pyc = (float)row * (IMG_H / (float)(HH - 1));

    // query (raw)
    const float4* qptr = (const float4*)(g_val + ((size_t)(b*NN + 0) * PP + p) * DDIM);
    float4 q4 = qptr[lane];
    float qss = wred(q4.x*q4.x + q4.y*q4.y + q4.z*q4.z + q4.w*q4.w);
    float qinv = 1.f / fmaxf(sqrtf(qss), 1e-12f);

    float4 s4[NN];
    float dotv[NN];

    #pragma unroll
    for (int n = 0; n < NN; n++) {
        const float* H = g_Hm + (b*NN + n) * 9;
        float hz = fmaf(H[6], pxc, fmaf(H[7], pyc, H[8]));
        float hx = fmaf(H[0], pxc, fmaf(H[1], pyc, H[2])) / hz;
        float hy = fmaf(H[3], pxc, fmaf(H[4], pyc, H[5])) / hz;
        float sx = hx * ((float)WW / IMG_W);
        float sy = hy * ((float)HH / IMG_H);
        bool valid = (sx >= 0.f) && (sx <= (float)(WW-1)) &&
                     (sy >= 0.f) && (sy <= (float)(HH-1));
        sx = fminf(fmaxf(sx, -1e4f), 1e4f);
        sy = fminf(fmaxf(sy, -1e4f), 1e4f);
        float x0f = floorf(sx), y0f = floorf(sy);
        int   x0 = (int)x0f,    y0 = (int)y0f;
        float fx = sx - x0f, fy = sy - y0f;

        float4 acc = make_float4(0.f, 0.f, 0.f, 0.f);
        const float* vb = g_val + (size_t)(b*NN + n) * PP * DDIM;
        #pragma unroll
        for (int c = 0; c < 4; c++) {
            int cx = x0 + (c & 1);
            int cy = y0 + (c >> 1);
            float wx = (c & 1)  ? fx : 1.f - fx;
            float wy = (c >> 1) ? fy : 1.f - fy;
            if (cx >= 0 && cx < WW && cy >= 0 && cy < HH) {
                const float4* vp = (const float4*)(vb + ((size_t)(cy*WW + cx)) * DDIM) + lane;
                float4 v = *vp;
                float w = wx * wy;
                acc.x = fmaf(w, v.x, acc.x);
                acc.y = fmaf(w, v.y, acc.y);
                acc.z = fmaf(w, v.z, acc.z);
                acc.w = fmaf(w, v.w, acc.w);
            }
        }
        s4[n] = acc;
        float ss = acc.x*acc.x + acc.y*acc.y + acc.z*acc.z + acc.w*acc.w;
        float dd = q4.x*acc.x + q4.y*acc.y + q4.z*acc.z + q4.w*acc.w;
        #pragma unroll
        for (int o = 16; o; o >>= 1) {
            ss += __shfl_xor_sync(0xffffffffu, ss, o);
            dd += __shfl_xor_sync(0xffffffffu, dd, o);
        }
        float sinv = 1.f / fmaxf(sqrtf(ss), 1e-12f);
        dotv[n] = valid ? dd * qinv * sinv : 0.f;
    }

    // softmax over n
    float m = dotv[0];
    #pragma unroll
    for (int n = 1; n < NN; n++) m = fmaxf(m, dotv[n]);
    float e[NN], se = 0.f;
    #pragma unroll
    for (int n = 0; n < NN; n++) { e[n] = expf(dotv[n] - m); se += e[n]; }
    float inv = 1.f / se;

    float4 o = q4;  // residual: + query
    #pragma unroll
    for (int n = 0; n < NN; n++) {
        float a = e[n] * inv;
        o.x = fmaf(a, s4[n].x, o.x);
        o.y = fmaf(a, s4[n].y, o.y);
        o.z = fmaf(a, s4[n].z, o.z);
        o.w = fmaf(a, s4[n].w, o.w);
    }
    float4* zp = (float4*)(g_z + ((size_t)b * PP + p) * DDIM);
    zp[lane] = o;
}

// ---------------------------------------------------------------------------
// K3: LN1 -> MLP(gelu) -> residual -> LN2 -> transposed store
// 16 pixels per block, 256 threads
// ---------------------------------------------------------------------------
__global__ void __launch_bounds__(256) k3_mlp(const float* __restrict__ l1g,
                                              const float* __restrict__ l1b,
                                              const float* __restrict__ W1,
                                              const float* __restrict__ b1,
                                              const float* __restrict__ W2,
                                              const float* __restrict__ b2,
                                              const float* __restrict__ l2g,
                                              const float* __restrict__ l2b,
                                              float* __restrict__ out)
{
    __shared__ float xs[16][132];   // 132: float4-aligned pad
    __shared__ float hs[16][260];
    int b  = blockIdx.y;
    int p0 = blockIdx.x * 16;
    int t    = threadIdx.x;
    int lane = t & 31;
    int wid  = t >> 5;

    const float* zb = g_z + ((size_t)b * PP + p0) * DDIM;
    for (int i = t; i < 16*DDIM; i += 256) {
        int pp = i >> 7, d = i & 127;
        xs[pp][d] = zb[(size_t)pp * DDIM + d];
    }
    __syncthreads();

    // LN1 (warp handles 2 pixels)
    #pragma unroll
    for (int k = 0; k < 2; k++) {
        int pp = wid*2 + k;
        float v0 = xs[pp][lane], v1 = xs[pp][lane+32], v2 = xs[pp][lane+64], v3 = xs[pp][lane+96];
        float s  = wred(v0+v1+v2+v3);
        float s2 = wred(v0*v0+v1*v1+v2*v2+v3*v3);
        float mu = s * (1.f/128.f);
        float var = s2 * (1.f/128.f) - mu*mu;
        float rs = rsqrtf(var + 1e-5f);
        xs[pp][lane]    = (v0-mu)*rs*l1g[lane]    + l1b[lane];
        xs[pp][lane+32] = (v1-mu)*rs*l1g[lane+32] + l1b[lane+32];
        xs[pp][lane+64] = (v2-mu)*rs*l1g[lane+64] + l1b[lane+64];
        xs[pp][lane+96] = (v3-mu)*rs*l1g[lane+96] + l1b[lane+96];
    }
    __syncthreads();

    // GEMM1: thread j computes hidden unit j for all 16 pixels
    {
        int j = t;
        float acc[16];
        #pragma unroll
        for (int pp = 0; pp < 16; pp++) acc[pp] = 0.f;
        const float* w1c = W1 + j;   // W1[d][j], stride 256
        #pragma unroll 4
        for (int d4 = 0; d4 < 32; d4++) {
            float w0 = w1c[(d4*4+0)*256];
            float w1v = w1c[(d4*4+1)*256];
            float w2v = w1c[(d4*4+2)*256];
            float w3 = w1c[(d4*4+3)*256];
            #pragma unroll
            for (int pp = 0; pp < 16; pp++) {
                float4 x = *(const float4*)&xs[pp][d4*4];
                acc[pp] = fmaf(x.x, w0,  acc[pp]);
                acc[pp] = fmaf(x.y, w1v, acc[pp]);
                acc[pp] = fmaf(x.z, w2v, acc[pp]);
                acc[pp] = fmaf(x.w, w3,  acc[pp]);
            }
        }
        float bj = b1[j];
        #pragma unroll
        for (int pp = 0; pp < 16; pp++) {
            float h = acc[pp] + bj;
            hs[pp][j] = 0.5f * h * (1.f + erff(h * 0.70710678118654752f));
        }
    }
    __syncthreads();

    // GEMM2: 128 d-lanes x 2 pixel halves; 8 pixels each
    {
        int d = t & 127;
        int half = t >> 7;
        float acc2[8];
        #pragma unroll
        for (int i = 0; i < 8; i++) acc2[i] = 0.f;
        const float* w2c = W2 + d;   // W2[k][d], stride 128
        #pragma unroll 4
        for (int k4 = 0; k4 < 64; k4++) {
            float w0 = w2c[(k4*4+0)*128];
            float w1v = w2c[(k4*4+1)*128];
            float w2v = w2c[(k4*4+2)*128];
            float w3 = w2c[(k4*4+3)*128];
            #pragma unroll
            for (int i = 0; i < 8; i++) {
                int pp = half*8 + i;
                float4 h = *(const float4*)&hs[pp][k4*4];
                acc2[i] = fmaf(h.x, w0,  acc2[i]);
                acc2[i] = fmaf(h.y, w1v, acc2[i]);
                acc2[i] = fmaf(h.z, w2v, acc2[i]);
                acc2[i] = fmaf(h.w, w3,  acc2[i]);
            }
        }
        float bd = b2[d];
        #pragma unroll
        for (int i = 0; i < 8; i++) {
            int pp = half*8 + i;
            xs[pp][d] = xs[pp][d] + acc2[i] + bd;  // residual (owner-only r/w)
        }
    }
    __syncthreads();

    // LN2
    #pragma unroll
    for (int k = 0; k < 2; k++) {
        int pp = wid*2 + k;
        float v0 = xs[pp][lane], v1 = xs[pp][lane+32], v2 = xs[pp][lane+64], v3 = xs[pp][lane+96];
        float s  = wred(v0+v1+v2+v3);
        float s2 = wred(v0*v0+v1*v1+v2*v2+v3*v3);
        float mu = s * (1.f/128.f);
        float var = s2 * (1.f/128.f) - mu*mu;
        float rs = rsqrtf(var + 1e-5f);
        xs[pp][lane]    = (v0-mu)*rs*l2g[lane]    + l2b[lane];
        xs[pp][lane+32] = (v1-mu)*rs*l2g[lane+32] + l2b[lane+32];
        xs[pp][lane+64] = (v2-mu)*rs*l2g[lane+64] + l2b[lane+64];
        xs[pp][lane+96] = (v3-mu)*rs*l2g[lane+96] + l2b[lane+96];
    }
    __syncthreads();

    // transposed store: out[b][d][p]
    for (int i = t; i < 16*DDIM; i += 256) {
        int d = i >> 4, pp = i & 15;
        out[((size_t)b * DDIM + d) * PP + p0 + pp] = xs[pp][d];
    }
}

// ---------------------------------------------------------------------------
extern "C" void kernel_launch(void* const* d_in, const int* in_sizes, int n_in,
                              void* d_out, int out_size)
{
    const float* feature   = (const float*)d_in[0];
    const float* I_src     = (const float*)d_in[1];
    const float* I_tar_inv = (const float*)d_in[2];
    const float* E         = (const float*)d_in[3];
    const float* dis       = (const float*)d_in[4];
    const float* norm_vec  = (const float*)d_in[5];
    const float* bn_gamma  = (const float*)d_in[6];
    const float* bn_beta   = (const float*)d_in[7];
    const float* bn_mean   = (const float*)d_in[8];
    const float* bn_var    = (const float*)d_in[9];
    const float* conv_w    = (const float*)d_in[10];
    const float* ln1_g     = (const float*)d_in[11];
    const float* ln1_b     = (const float*)d_in[12];
    const float* mlp_w1    = (const float*)d_in[13];
    const float* mlp_b1    = (const float*)d_in[14];
    const float* mlp_w2    = (const float*)d_in[15];
    const float* mlp_b2    = (const float*)d_in[16];
    const float* ln2_g     = (const float*)d_in[17];
    const float* ln2_b     = (const float*)d_in[18];
    float* out = (float*)d_out;

    k0_prep<<<1, 256>>>(I_src, I_tar_inv, E, dis, norm_vec,
                        bn_gamma, bn_beta, bn_mean, bn_var);
    k1_conv<<<dim3(PP/128, BN), 256>>>(feature, conv_w);
    k2_attn<<<dim3(PP/8, BB), 256>>>();
    k3_mlp<<<dim3(PP/16, BB), 256>>>(ln1_g, ln1_b, mlp_w1, mlp_b1,
                                     mlp_w2, mlp_b2, ln2_g, ln2_b, out);
}

// round 6
// speedup vs baseline: 1.4071x; 1.4071x over previous
#include <cuda_runtime.h>
#include <cuda_bf16.h>
#include <math.h>
#include <stdint.h>

// Problem constants
#define BB 4
#define NN 6
#define FDIM 256
#define DDIM 128
#define HH 64
#define WW 120
#define PP (HH*WW)          // 7680
#define BN (BB*NN)          // 24
#define IMG_H 480.0f
#define IMG_W 960.0f

// Scratch (device globals — no runtime allocation allowed)
__device__ float g_val[(size_t)BN * PP * DDIM];   // (bn, p, d)  94.4 MB
__device__ float g_z[(size_t)BB * PP * DDIM];     // (b, p, d)   15.7 MB
__device__ float g_Hm[BN * 9];
__device__ float g_bnscale[FDIM];
__device__ float g_bnshift[FDIM];

// ===========================================================================
// helpers: sm_80-baseline tensor path (ldmatrix + mma.sync) — no 'a' features
// ===========================================================================
__device__ __forceinline__ uint32_t smem_u32(const void* p) {
    uint32_t a;
    asm("{ .reg .u64 t; cvta.to.shared.u64 t, %1; cvt.u32.u64 %0, t; }"
        : "=r"(a) : "l"(p));
    return a;
}
__device__ __forceinline__ void ldsm_x4(uint32_t* r, uint32_t addr) {
    asm volatile("ldmatrix.sync.aligned.m8n8.x4.shared.b16 {%0,%1,%2,%3}, [%4];"
        : "=r"(r[0]), "=r"(r[1]), "=r"(r[2]), "=r"(r[3]) : "r"(addr));
}
__device__ __forceinline__ void mma_bf16(float* c, const uint32_t* a,
                                         uint32_t b0, uint32_t b1) {
    asm volatile(
        "mma.sync.aligned.m16n8k16.row.col.f32.bf16.bf16.f32 "
        "{%0,%1,%2,%3}, {%4,%5,%6,%7}, {%8,%9}, {%0,%1,%2,%3};"
        : "+f"(c[0]), "+f"(c[1]), "+f"(c[2]), "+f"(c[3])
        : "r"(a[0]), "r"(a[1]), "r"(a[2]), "r"(a[3]), "r"(b0), "r"(b1));
}
__device__ __forceinline__ uint32_t pack_bf16x2(__nv_bfloat16 lo, __nv_bfloat16 hi) {
    return ((uint32_t)__bfloat16_as_ushort(hi) << 16) | __bfloat16_as_ushort(lo);
}

// ---------------------------------------------------------------------------
// K0: homographies + BN scale/shift
// ---------------------------------------------------------------------------
__global__ void k0_prep(const float* __restrict__ I_src,
                        const float* __restrict__ I_tar_inv,
                        const float* __restrict__ E,
                        const float* __restrict__ disp,
                        const float* __restrict__ nvec,
                        const float* __restrict__ bng,
                        const float* __restrict__ bnb,
                        const float* __restrict__ bnm,
                        const float* __restrict__ bnv)
{
    int t = threadIdx.x;
    if (t < FDIM) {
        float sc = bng[t] * rsqrtf(bnv[t] + 1e-5f);
        g_bnscale[t] = sc;
        g_bnshift[t] = bnb[t] - bnm[t] * sc;
    }
    if (t < BN) {
        int b = t / NN;
        float dis = disp[0];
        const float* Eb = E + t * 16;
        const float* Ks = I_src + t * 9;
        const float* Kt = I_tar_inv + b * 9;
        float nv0 = nvec[b*3+0], nv1 = nvec[b*3+1], nv2 = nvec[b*3+2];
        float A[9];
        #pragma unroll
        for (int i = 0; i < 3; i++) {
            float Ti = Eb[i*4+3] / dis;
            A[i*3+0] = Eb[i*4+0] - Ti * nv0;
            A[i*3+1] = Eb[i*4+1] - Ti * nv1;
            A[i*3+2] = Eb[i*4+2] - Ti * nv2;
        }
        float M[9];
        #pragma unroll
        for (int i = 0; i < 3; i++)
            #pragma unroll
            for (int j = 0; j < 3; j++)
                M[i*3+j] = Ks[i*3+0]*A[0*3+j] + Ks[i*3+1]*A[1*3+j] + Ks[i*3+2]*A[2*3+j];
        #pragma unroll
        for (int i = 0; i < 3; i++)
            #pragma unroll
            for (int j = 0; j < 3; j++)
                g_Hm[t*9 + i*3+j] = M[i*3+0]*Kt[0*3+j] + M[i*3+1]*Kt[1*3+j] + M[i*3+2]*Kt[2*3+j];
    }
}

// ---------------------------------------------------------------------------
// K1 (HMMA): val[bn][p][d] = sum_f W[d][f]*relu(bn(feat)), split-bf16 x3 MMA
// CTA tile 128px(M) x 128d(N), K-chunks of 64. 8 warps: warp tile 32x64.
// smem: swizzled bf16 tiles, 128B rows (64 f per row).
// B (W) fragments: NON-trans ldmatrix — W is [n][k] row-major = col-major B.
// ---------------------------------------------------------------------------
#define S_XHI 0
#define S_XLO 16384
#define S_WHI 32768
#define S_WLO 49152
#define K1_SMEM 65536

__global__ void __launch_bounds__(256)
k1_conv_tc(const float* __restrict__ feat, const float* __restrict__ Wc)
{
    extern __shared__ char smem[];
    const uint32_t sb = smem_u32(smem);
    const int bn = blockIdx.y;
    const int p0 = blockIdx.x * 128;
    const int t  = threadIdx.x;
    const int wid = t >> 5, lane = t & 31;
    const int wm = wid & 3;    // M quarter: rows wm*32 .. +31
    const int wn = wid >> 2;   // N half:   cols wn*64 .. +63

    float acc[2][8][4];
    #pragma unroll
    for (int mi = 0; mi < 2; mi++)
        #pragma unroll
        for (int nt = 0; nt < 8; nt++)
            #pragma unroll
            for (int j = 0; j < 4; j++) acc[mi][nt][j] = 0.f;

    const float* fb = feat + (size_t)bn * FDIM * PP + p0;

    for (int chunk = 0; chunk < 4; chunk++) {
        const int f0 = chunk * 64;

        // --- produce X tiles: rows = 128 pixels, 64 f per row (bf16x2 packed) ---
        #pragma unroll 4
        for (int i = 0; i < 16; i++) {
            int idx = t + i * 256;          // 0..4095
            int pl = idx & 127;             // pixel row
            int fp = idx >> 7;              // f pair 0..31
            int f  = f0 + fp * 2;
            float v0 = fb[(size_t)f       * PP + pl];
            float v1 = fb[(size_t)(f + 1) * PP + pl];
            v0 = fmaxf(fmaf(v0, g_bnscale[f],   g_bnshift[f]),   0.f);
            v1 = fmaxf(fmaf(v1, g_bnscale[f+1], g_bnshift[f+1]), 0.f);
            __nv_bfloat16 h0 = __float2bfloat16(v0);
            __nv_bfloat16 h1 = __float2bfloat16(v1);
            __nv_bfloat16 l0 = __float2bfloat16(v0 - __bfloat162float(h0));
            __nv_bfloat16 l1 = __float2bfloat16(v1 - __bfloat162float(h1));
            uint32_t off = (uint32_t)pl * 128 + (((uint32_t)fp * 4) ^ ((pl & 7) << 4));
            *(uint32_t*)(smem + S_XHI + off) = pack_bf16x2(h0, h1);
            *(uint32_t*)(smem + S_XLO + off) = pack_bf16x2(l0, l1);
        }
        // --- produce W tiles: rows = 128 d, 64 f per row ---
        #pragma unroll 4
        for (int i = 0; i < 16; i++) {
            int idx = t + i * 256;
            int fp = idx & 31;              // f pair
            int dl = idx >> 5;              // d row
            float2 w = *(const float2*)(Wc + dl * FDIM + f0 + fp * 2);
            __nv_bfloat16 h0 = __float2bfloat16(w.x);
            __nv_bfloat16 h1 = __float2bfloat16(w.y);
            __nv_bfloat16 l0 = __float2bfloat16(w.x - __bfloat162float(h0));
            __nv_bfloat16 l1 = __float2bfloat16(w.y - __bfloat162float(h1));
            uint32_t off = (uint32_t)dl * 128 + (((uint32_t)fp * 4) ^ ((dl & 7) << 4));
            *(uint32_t*)(smem + S_WHI + off) = pack_bf16x2(h0, h1);
            *(uint32_t*)(smem + S_WLO + off) = pack_bf16x2(l0, l1);
        }
        __syncthreads();

        // --- consume: 4 k16 steps ---
        #pragma unroll
        for (int ks = 0; ks < 4; ks++) {
            const uint32_t kb = (uint32_t)ks * 32;   // byte offset of k-step
            // A fragments (hi & lo) for mi = 0,1
            uint32_t ah[2][4], al[2][4];
            #pragma unroll
            for (int mi = 0; mi < 2; mi++) {
                uint32_t row = (uint32_t)(wm * 32 + mi * 16 + (lane & 15));
                uint32_t kby = kb + ((lane >> 4) << 4);
                uint32_t off = row * 128 + (kby ^ ((row & 7) << 4));
                ldsm_x4(ah[mi], sb + S_XHI + off);
                ldsm_x4(al[mi], sb + S_XLO + off);
            }
            // B fragments: NON-trans x4 covers 2 n-tiles (16 n-rows) per load.
            // lanes 0-7: n rows +0..7 @ k-lo; 8-15: same rows @ k-hi;
            // 16-23: rows +8..15 @ k-lo; 24-31: rows +8..15 @ k-hi
            // -> r0,r1 = (b0,b1) for n-tile0; r2,r3 = (b0,b1) for n-tile1
            #pragma unroll
            for (int bj = 0; bj < 4; bj++) {
                uint32_t rown = (uint32_t)(wn * 64 + bj * 16 + (lane & 7) + ((lane >> 4) << 3));
                uint32_t kby  = kb + (((lane >> 3) & 1) << 4);
                uint32_t off  = rown * 128 + (kby ^ ((rown & 7) << 4));
                uint32_t bh[4], bl[4];
                ldsm_x4(bh, sb + S_WHI + off);
                ldsm_x4(bl, sb + S_WLO + off);
                #pragma unroll
                for (int mi = 0; mi < 2; mi++) {
                    mma_bf16(acc[mi][bj*2+0], ah[mi], bh[0], bh[1]);
                    mma_bf16(acc[mi][bj*2+0], ah[mi], bl[0], bl[1]);
                    mma_bf16(acc[mi][bj*2+0], al[mi], bh[0], bh[1]);
                    mma_bf16(acc[mi][bj*2+1], ah[mi], bh[2], bh[3]);
                    mma_bf16(acc[mi][bj*2+1], ah[mi], bl[2], bl[3]);
                    mma_bf16(acc[mi][bj*2+1], al[mi], bh[2], bh[3]);
                }
            }
        }
        __syncthreads();
    }

    // --- epilogue: D fragment -> g_val[(bn,p),d] ---
    const int qr = lane >> 2, qc = lane & 3;
    #pragma unroll
    for (int mi = 0; mi < 2; mi++) {
        int row0 = p0 + wm * 32 + mi * 16 + qr;
        float* r0 = g_val + ((size_t)bn * PP + row0) * DDIM;
        float* r1 = r0 + 8 * DDIM;
        #pragma unroll
        for (int nt = 0; nt < 8; nt++) {
            int col = wn * 64 + nt * 8 + qc * 2;
            *(float2*)(r0 + col) = make_float2(acc[mi][nt][0], acc[mi][nt][1]);
            *(float2*)(r1 + col) = make_float2(acc[mi][nt][2], acc[mi][nt][3]);
        }
    }
}

// ---------------------------------------------------------------------------
// K2: homography + bilinear sample + normalized dot + softmax + weighted sum
// ---------------------------------------------------------------------------
__device__ __forceinline__ float wred(float v) {
    #pragma unroll
    for (int o = 16; o; o >>= 1) v += __shfl_xor_sync(0xffffffffu, v, o);
    return v;
}

__global__ void __launch_bounds__(256) k2_attn()
{
    int b    = blockIdx.y;
    int p    = blockIdx.x * 8 + (threadIdx.x >> 5);
    int lane = threadIdx.x & 31;

    int col = p % WW, row = p / WW;
    float pxc = (float)col * (IMG_W / (float)(WW - 1));
    float pyc = (float)row * (IMG_H / (float)(HH - 1));

    const float4* qptr = (const float4*)(g_val + ((size_t)(b*NN + 0) * PP + p) * DDIM);
    float4 q4 = qptr[lane];
    float qss = wred(q4.x*q4.x + q4.y*q4.y + q4.z*q4.z + q4.w*q4.w);
    float qinv = 1.f / fmaxf(sqrtf(qss), 1e-12f);

    float4 s4[NN];
    float dotv[NN];

    #pragma unroll
    for (int n = 0; n < NN; n++) {
        const float* H = g_Hm + (b*NN + n) * 9;
        float hz = fmaf(H[6], pxc, fmaf(H[7], pyc, H[8]));
        float hx = fmaf(H[0], pxc, fmaf(H[1], pyc, H[2])) / hz;
        float hy = fmaf(H[3], pxc, fmaf(H[4], pyc, H[5])) / hz;
        float sx = hx * ((float)WW / IMG_W);
        float sy = hy * ((float)HH / IMG_H);
        bool valid = (sx >= 0.f) && (sx <= (float)(WW-1)) &&
                     (sy >= 0.f) && (sy <= (float)(HH-1));
        sx = fminf(fmaxf(sx, -1e4f), 1e4f);
        sy = fminf(fmaxf(sy, -1e4f), 1e4f);
        float x0f = floorf(sx), y0f = floorf(sy);
        int   x0 = (int)x0f,    y0 = (int)y0f;
        float fx = sx - x0f, fy = sy - y0f;

        float4 acc = make_float4(0.f, 0.f, 0.f, 0.f);
        const float* vb = g_val + (size_t)(b*NN + n) * PP * DDIM;
        #pragma unroll
        for (int c = 0; c < 4; c++) {
            int cx = x0 + (c & 1);
            int cy = y0 + (c >> 1);
            float wx = (c & 1)  ? fx : 1.f - fx;
            float wy = (c >> 1) ? fy : 1.f - fy;
            if (cx >= 0 && cx < WW && cy >= 0 && cy < HH) {
                const float4* vp = (const float4*)(vb + ((size_t)(cy*WW + cx)) * DDIM) + lane;
                float4 v = *vp;
                float w = wx * wy;
                acc.x = fmaf(w, v.x, acc.x);
                acc.y = fmaf(w, v.y, acc.y);
                acc.z = fmaf(w, v.z, acc.z);
                acc.w = fmaf(w, v.w, acc.w);
            }
        }
        s4[n] = acc;
        float ss = acc.x*acc.x + acc.y*acc.y + acc.z*acc.z + acc.w*acc.w;
        float dd = q4.x*acc.x + q4.y*acc.y + q4.z*acc.z + q4.w*acc.w;
        #pragma unroll
        for (int o = 16; o; o >>= 1) {
            ss += __shfl_xor_sync(0xffffffffu, ss, o);
            dd += __shfl_xor_sync(0xffffffffu, dd, o);
        }
        float sinv = 1.f / fmaxf(sqrtf(ss), 1e-12f);
        dotv[n] = valid ? dd * qinv * sinv : 0.f;
    }

    float m = dotv[0];
    #pragma unroll
    for (int n = 1; n < NN; n++) m = fmaxf(m, dotv[n]);
    float e[NN], se = 0.f;
    #pragma unroll
    for (int n = 0; n < NN; n++) { e[n] = expf(dotv[n] - m); se += e[n]; }
    float inv = 1.f / se;

    float4 o = q4;
    #pragma unroll
    for (int n = 0; n < NN; n++) {
        float a = e[n] * inv;
        o.x = fmaf(a, s4[n].x, o.x);
        o.y = fmaf(a, s4[n].y, o.y);
        o.z = fmaf(a, s4[n].z, o.z);
        o.w = fmaf(a, s4[n].w, o.w);
    }
    float4* zp = (float4*)(g_z + ((size_t)b * PP + p) * DDIM);
    zp[lane] = o;
}

// ---------------------------------------------------------------------------
// K3: LN1 -> MLP(gelu) -> residual -> LN2 -> transposed store
// 32 pixels per block, 256 threads, dynamic smem
// ---------------------------------------------------------------------------
#define K3_XS_STRIDE 132
#define K3_HS_STRIDE 260
#define K3_XS_BYTES (32 * K3_XS_STRIDE * 4)
#define K3_SMEM (K3_XS_BYTES + 32 * K3_HS_STRIDE * 4)

__global__ void __launch_bounds__(256) k3_mlp(const float* __restrict__ l1g,
                                              const float* __restrict__ l1b,
                                              const float* __restrict__ W1,
                                              const float* __restrict__ b1,
                                              const float* __restrict__ W2,
                                              const float* __restrict__ b2,
                                              const float* __restrict__ l2g,
                                              const float* __restrict__ l2b,
                                              float* __restrict__ out)
{
    extern __shared__ char k3smem[];
    float (*xs)[K3_XS_STRIDE] = (float(*)[K3_XS_STRIDE])k3smem;
    float (*hs)[K3_HS_STRIDE] = (float(*)[K3_HS_STRIDE])(k3smem + K3_XS_BYTES);

    int b  = blockIdx.y;
    int p0 = blockIdx.x * 32;
    int t    = threadIdx.x;
    int lane = t & 31;
    int wid  = t >> 5;

    const float* zb = g_z + ((size_t)b * PP + p0) * DDIM;
    for (int i = t; i < 32*DDIM; i += 256) {
        int pp = i >> 7, d = i & 127;
        xs[pp][d] = zb[(size_t)pp * DDIM + d];
    }
    __syncthreads();

    // LN1 (each warp: 4 pixels)
    #pragma unroll
    for (int k = 0; k < 4; k++) {
        int pp = wid*4 + k;
        float v0 = xs[pp][lane], v1 = xs[pp][lane+32], v2 = xs[pp][lane+64], v3 = xs[pp][lane+96];
        float s  = wred(v0+v1+v2+v3);
        float s2 = wred(v0*v0+v1*v1+v2*v2+v3*v3);
        float mu = s * (1.f/128.f);
        float var = s2 * (1.f/128.f) - mu*mu;
        float rs = rsqrtf(var + 1e-5f);
        xs[pp][lane]    = (v0-mu)*rs*l1g[lane]    + l1b[lane];
        xs[pp][lane+32] = (v1-mu)*rs*l1g[lane+32] + l1b[lane+32];
        xs[pp][lane+64] = (v2-mu)*rs*l1g[lane+64] + l1b[lane+64];
        xs[pp][lane+96] = (v3-mu)*rs*l1g[lane+96] + l1b[lane+96];
    }
    __syncthreads();

    // GEMM1: thread j computes hidden unit j for all 32 pixels
    {
        int j = t;
        float acc[32];
        #pragma unroll
        for (int pp = 0; pp < 32; pp++) acc[pp] = 0.f;
        const float* w1c = W1 + j;
        #pragma unroll 2
        for (int d4 = 0; d4 < 32; d4++) {
            float w0  = w1c[(d4*4+0)*256];
            float w1v = w1c[(d4*4+1)*256];
            float w2v = w1c[(d4*4+2)*256];
            float w3  = w1c[(d4*4+3)*256];
            #pragma unroll
            for (int pp = 0; pp < 32; pp++) {
                float4 x = *(const float4*)&xs[pp][d4*4];
                acc[pp] = fmaf(x.x, w0,  acc[pp]);
                acc[pp] = fmaf(x.y, w1v, acc[pp]);
                acc[pp] = fmaf(x.z, w2v, acc[pp]);
                acc[pp] = fmaf(x.w, w3,  acc[pp]);
            }
        }
        float bj = b1[j];
        #pragma unroll
        for (int pp = 0; pp < 32; pp++) {
            float h = acc[pp] + bj;
            hs[pp][j] = 0.5f * h * (1.f + erff(h * 0.70710678118654752f));
        }
    }
    __syncthreads();

    // GEMM2: 128 d-lanes x 2 halves; 16 pixels each
    {
        int d = t & 127;
        int half = t >> 7;
        float acc2[16];
        #pragma unroll
        for (int i = 0; i < 16; i++) acc2[i] = 0.f;
        const float* w2c = W2 + d;
        #pragma unroll 2
        for (int k4 = 0; k4 < 64; k4++) {
            float w0  = w2c[(k4*4+0)*128];
            float w1v = w2c[(k4*4+1)*128];
            float w2v = w2c[(k4*4+2)*128];
            float w3  = w2c[(k4*4+3)*128];
            #pragma unroll
            for (int i = 0; i < 16; i++) {
                int pp = half*16 + i;
                float4 h = *(const float4*)&hs[pp][k4*4];
                acc2[i] = fmaf(h.x, w0,  acc2[i]);
                acc2[i] = fmaf(h.y, w1v, acc2[i]);
                acc2[i] = fmaf(h.z, w2v, acc2[i]);
                acc2[i] = fmaf(h.w, w3,  acc2[i]);
            }
        }
        float bd = b2[d];
        #pragma unroll
        for (int i = 0; i < 16; i++) {
            int pp = half*16 + i;
            xs[pp][d] = xs[pp][d] + acc2[i] + bd;
        }
    }
    __syncthreads();

    // LN2
    #pragma unroll
    for (int k = 0; k < 4; k++) {
        int pp = wid*4 + k;
        float v0 = xs[pp][lane], v1 = xs[pp][lane+32], v2 = xs[pp][lane+64], v3 = xs[pp][lane+96];
        float s  = wred(v0+v1+v2+v3);
        float s2 = wred(v0*v0+v1*v1+v2*v2+v3*v3);
        float mu = s * (1.f/128.f);
        float var = s2 * (1.f/128.f) - mu*mu;
        float rs = rsqrtf(var + 1e-5f);
        xs[pp][lane]    = (v0-mu)*rs*l2g[lane]    + l2b[lane];
        xs[pp][lane+32] = (v1-mu)*rs*l2g[lane+32] + l2b[lane+32];
        xs[pp][lane+64] = (v2-mu)*rs*l2g[lane+64] + l2b[lane+64];
        xs[pp][lane+96] = (v3-mu)*rs*l2g[lane+96] + l2b[lane+96];
    }
    __syncthreads();

    // transposed store: out[b][d][p] — 32 consecutive p per row
    for (int i = t; i < 32*DDIM; i += 256) {
        int d = i >> 5, pp = i & 31;
        out[((size_t)b * DDIM + d) * PP + p0 + pp] = xs[pp][d];
    }
}

// ---------------------------------------------------------------------------
extern "C" void kernel_launch(void* const* d_in, const int* in_sizes, int n_in,
                              void* d_out, int out_size)
{
    const float* feature   = (const float*)d_in[0];
    const float* I_src     = (const float*)d_in[1];
    const float* I_tar_inv = (const float*)d_in[2];
    const float* E         = (const float*)d_in[3];
    const float* dis       = (const float*)d_in[4];
    const float* norm_vec  = (const float*)d_in[5];
    const float* bn_gamma  = (const float*)d_in[6];
    const float* bn_beta   = (const float*)d_in[7];
    const float* bn_mean   = (const float*)d_in[8];
    const float* bn_var    = (const float*)d_in[9];
    const float* conv_w    = (const float*)d_in[10];
    const float* ln1_g     = (const float*)d_in[11];
    const float* ln1_b     = (const float*)d_in[12];
    const float* mlp_w1    = (const float*)d_in[13];
    const float* mlp_b1    = (const float*)d_in[14];
    const float* mlp_w2    = (const float*)d_in[15];
    const float* mlp_b2    = (const float*)d_in[16];
    const float* ln2_g     = (const float*)d_in[17];
    const float* ln2_b     = (const float*)d_in[18];
    float* out = (float*)d_out;

    cudaFuncSetAttribute(k1_conv_tc,
                         cudaFuncAttributeMaxDynamicSharedMemorySize, K1_SMEM);
    cudaFuncSetAttribute(k3_mlp,
                         cudaFuncAttributeMaxDynamicSharedMemorySize, K3_SMEM);

    k0_prep<<<1, 256>>>(I_src, I_tar_inv, E, dis, norm_vec,
                        bn_gamma, bn_beta, bn_mean, bn_var);
    k1_conv_tc<<<dim3(PP/128, BN), 256, K1_SMEM>>>(feature, conv_w);
    k2_attn<<<dim3(PP/8, BB), 256>>>();
    k3_mlp<<<dim3(PP/32, BB), 256, K3_SMEM>>>(ln1_g, ln1_b, mlp_w1, mlp_b1,
                                              mlp_w2, mlp_b2, ln2_g, ln2_b, out);
}

// round 9
// speedup vs baseline: 2.1154x; 1.5034x over previous
#include <cuda_runtime.h>
#include <cuda_bf16.h>
#include <math.h>
#include <stdint.h>

// Problem constants
#define BB 4
#define NN 6
#define FDIM 256
#define DDIM 128
#define HH 64
#define WW 120
#define PP (HH*WW)          // 7680
#define BN (BB*NN)          // 24
#define IMG_H 480.0f
#define IMG_W 960.0f

// Scratch (device globals — no runtime allocation allowed)
__device__ float g_val[(size_t)BN * PP * DDIM];   // (bn, p, d)  94.4 MB
__device__ float g_z[(size_t)BB * PP * DDIM];     // (b, p, d)   15.7 MB
__device__ float g_Hm[BN * 9];
__device__ float g_bnscale[FDIM];
__device__ float g_bnshift[FDIM];
// Prepacked split-bf16 weights: .x = hi pair (k, k+1), .y = lo pair
__device__ uint2 g_wcp[128 * 128];   // conv_w   [d=128][kpair=128]  (k = f)
__device__ uint2 g_w1p[256 * 64];    // W1^T     [n=256][kpair=64]   (k = d)
__device__ uint2 g_w2p[128 * 128];   // W2^T     [n=128][kpair=128]  (k = j)

// ===========================================================================
// helpers: sm_80-baseline tensor path (ldmatrix + mma.sync) — no 'a' features
// ===========================================================================
__device__ __forceinline__ uint32_t smem_u32(const void* p) {
    uint32_t a;
    asm("{ .reg .u64 t; cvta.to.shared.u64 t, %1; cvt.u32.u64 %0, t; }"
        : "=r"(a) : "l"(p));
    return a;
}
__device__ __forceinline__ void ldsm_x4(uint32_t* r, uint32_t addr) {
    asm volatile("ldmatrix.sync.aligned.m8n8.x4.shared.b16 {%0,%1,%2,%3}, [%4];"
        : "=r"(r[0]), "=r"(r[1]), "=r"(r[2]), "=r"(r[3]) : "r"(addr));
}
__device__ __forceinline__ void mma_bf16(float* c, const uint32_t* a,
                                         uint32_t b0, uint32_t b1) {
    asm volatile(
        "mma.sync.aligned.m16n8k16.row.col.f32.bf16.bf16.f32 "
        "{%0,%1,%2,%3}, {%4,%5,%6,%7}, {%8,%9}, {%0,%1,%2,%3};"
        : "+f"(c[0]), "+f"(c[1]), "+f"(c[2]), "+f"(c[3])
        : "r"(a[0]), "r"(a[1]), "r"(a[2]), "r"(a[3]), "r"(b0), "r"(b1));
}
__device__ __forceinline__ uint32_t pack_bf16x2(__nv_bfloat16 lo, __nv_bfloat16 hi) {
    return ((uint32_t)__bfloat16_as_ushort(hi) << 16) | __bfloat16_as_ushort(lo);
}
__device__ __forceinline__ uint2 split_pack(float a, float b) {
    __nv_bfloat16 ha = __float2bfloat16(a), hb = __float2bfloat16(b);
    __nv_bfloat16 la = __float2bfloat16(a - __bfloat162float(ha));
    __nv_bfloat16 lb = __float2bfloat16(b - __bfloat162float(hb));
    return make_uint2(pack_bf16x2(ha, hb), pack_bf16x2(la, lb));
}
__device__ __forceinline__ float bflo_f(uint32_t u) { return __uint_as_float(u << 16); }
__device__ __forceinline__ float bfhi_f(uint32_t u) { return __uint_as_float(u & 0xffff0000u); }
__device__ __forceinline__ float geluf(float h) {
    return 0.5f * h * (1.f + erff(h * 0.70710678118654752f));
}
__device__ __forceinline__ float wred(float v) {
    #pragma unroll
    for (int o = 16; o; o >>= 1) v += __shfl_xor_sync(0xffffffffu, v, o);
    return v;
}

// ---------------------------------------------------------------------------
// K0: homographies + BN scale/shift
// ---------------------------------------------------------------------------
__global__ void k0_prep(const float* __restrict__ I_src,
                        const float* __restrict__ I_tar_inv,
                        const float* __restrict__ E,
                        const float* __restrict__ disp,
                        const float* __restrict__ nvec,
                        const float* __restrict__ bng,
                        const float* __restrict__ bnb,
                        const float* __restrict__ bnm,
                        const float* __restrict__ bnv)
{
    int t = threadIdx.x;
    if (t < FDIM) {
        float sc = bng[t] * rsqrtf(bnv[t] + 1e-5f);
        g_bnscale[t] = sc;
        g_bnshift[t] = bnb[t] - bnm[t] * sc;
    }
    if (t < BN) {
        int b = t / NN;
        float dis = disp[0];
        const float* Eb = E + t * 16;
        const float* Ks = I_src + t * 9;
        const float* Kt = I_tar_inv + b * 9;
        float nv0 = nvec[b*3+0], nv1 = nvec[b*3+1], nv2 = nvec[b*3+2];
        float A[9];
        #pragma unroll
        for (int i = 0; i < 3; i++) {
            float Ti = Eb[i*4+3] / dis;
            A[i*3+0] = Eb[i*4+0] - Ti * nv0;
            A[i*3+1] = Eb[i*4+1] - Ti * nv1;
            A[i*3+2] = Eb[i*4+2] - Ti * nv2;
        }
        float M[9];
        #pragma unroll
        for (int i = 0; i < 3; i++)
            #pragma unroll
            for (int j = 0; j < 3; j++)
                M[i*3+j] = Ks[i*3+0]*A[0*3+j] + Ks[i*3+1]*A[1*3+j] + Ks[i*3+2]*A[2*3+j];
        #pragma unroll
        for (int i = 0; i < 3; i++)
            #pragma unroll
            for (int j = 0; j < 3; j++)
                g_Hm[t*9 + i*3+j] = M[i*3+0]*Kt[0*3+j] + M[i*3+1]*Kt[1*3+j] + M[i*3+2]*Kt[2*3+j];
    }
}

// ---------------------------------------------------------------------------
// K0b: pack weights to split-bf16 transposed layouts
// ---------------------------------------------------------------------------
__global__ void k0b_pack(const float* __restrict__ Wc,
                         const float* __restrict__ W1,
                         const float* __restrict__ W2)
{
    int i = blockIdx.x * 256 + threadIdx.x;   // 0..16383
    {   // conv_w [128 d][256 f] -> g_wcp[d][fpair]
        int d = i >> 7, fp = i & 127;
        g_wcp[i] = split_pack(Wc[d*256 + fp*2], Wc[d*256 + fp*2 + 1]);
    }
    {   // W2^T: g_w2p[n=d][kpair over j], W2 is [256 j][128 d]
        int d = i >> 7, kp = i & 127;
        g_w2p[i] = split_pack(W2[(kp*2)*128 + d], W2[(kp*2+1)*128 + d]);
    }
    {   // W1^T: g_w1p[n=j][kpair over d], W1 is [128 d][256 j]
        int j = i >> 6, kp = i & 63;   // i < 16384 = 256*64 exactly
        g_w1p[i] = split_pack(W1[(kp*2)*256 + j], W1[(kp*2+1)*256 + j]);
    }
}

// ---------------------------------------------------------------------------
// K1 (HMMA): val[bn][p][d] = sum_f W[d][f]*relu(bn(feat)), split-bf16 x3 MMA
// ---------------------------------------------------------------------------
#define S_XHI 0
#define S_XLO 16384
#define S_WHI 32768
#define S_WLO 49152
#define K1_SMEM 65536

__global__ void __launch_bounds__(256)
k1_conv_tc(const float* __restrict__ feat)
{
    extern __shared__ char smem[];
    const uint32_t sb = smem_u32(smem);
    const int bn = blockIdx.y;
    const int p0 = blockIdx.x * 128;
    const int t  = threadIdx.x;
    const int wid = t >> 5, lane = t & 31;
    const int wm = wid & 3;    // M quarter
    const int wn = wid >> 2;   // N half

    float acc[2][8][4];
    #pragma unroll
    for (int mi = 0; mi < 2; mi++)
        #pragma unroll
        for (int nt = 0; nt < 8; nt++)
            #pragma unroll
            for (int j = 0; j < 4; j++) acc[mi][nt][j] = 0.f;

    const float* fb = feat + (size_t)bn * FDIM * PP + p0;

    for (int chunk = 0; chunk < 4; chunk++) {
        const int f0 = chunk * 64;
        // X tiles: 128 px rows, 64 f (bf16x2 pairs), swizzled
        #pragma unroll 4
        for (int i = 0; i < 16; i++) {
            int idx = t + i * 256;
            int pl = idx & 127;
            int fp = idx >> 7;
            int f  = f0 + fp * 2;
            float v0 = fb[(size_t)f       * PP + pl];
            float v1 = fb[(size_t)(f + 1) * PP + pl];
            v0 = fmaxf(fmaf(v0, g_bnscale[f],   g_bnshift[f]),   0.f);
            v1 = fmaxf(fmaf(v1, g_bnscale[f+1], g_bnshift[f+1]), 0.f);
            uint2 p = split_pack(v0, v1);
            uint32_t off = (uint32_t)pl * 128 + (((uint32_t)fp * 4) ^ ((pl & 7) << 4));
            *(uint32_t*)(smem + S_XHI + off) = p.x;
            *(uint32_t*)(smem + S_XLO + off) = p.y;
        }
        // W tiles from prepacked global
        #pragma unroll 4
        for (int i = 0; i < 16; i++) {
            int idx = t + i * 256;
            int fpl = idx & 31;
            int dl  = idx >> 5;
            uint2 w = g_wcp[dl * 128 + chunk * 32 + fpl];
            uint32_t off = (uint32_t)dl * 128 + (((uint32_t)fpl * 4) ^ ((dl & 7) << 4));
            *(uint32_t*)(smem + S_WHI + off) = w.x;
            *(uint32_t*)(smem + S_WLO + off) = w.y;
        }
        __syncthreads();

        #pragma unroll
        for (int ks = 0; ks < 4; ks++) {
            const uint32_t kb = (uint32_t)ks * 32;
            uint32_t ah[2][4], al[2][4];
            #pragma unroll
            for (int mi = 0; mi < 2; mi++) {
                uint32_t row = (uint32_t)(wm * 32 + mi * 16 + (lane & 15));
                uint32_t kby = kb + ((lane >> 4) << 4);
                uint32_t off = row * 128 + (kby ^ ((row & 7) << 4));
                ldsm_x4(ah[mi], sb + S_XHI + off);
                ldsm_x4(al[mi], sb + S_XLO + off);
            }
            #pragma unroll
            for (int bj = 0; bj < 4; bj++) {
                uint32_t rown = (uint32_t)(wn * 64 + bj * 16 + (lane & 7) + ((lane >> 4) << 3));
                uint32_t kby  = kb + (((lane >> 3) & 1) << 4);
                uint32_t off  = rown * 128 + (kby ^ ((rown & 7) << 4));
                uint32_t bh[4], bl[4];
                ldsm_x4(bh, sb + S_WHI + off);
                ldsm_x4(bl, sb + S_WLO + off);
                #pragma unroll
                for (int mi = 0; mi < 2; mi++) {
                    mma_bf16(acc[mi][bj*2+0], ah[mi], bh[0], bh[1]);
                    mma_bf16(acc[mi][bj*2+0], ah[mi], bl[0], bl[1]);
                    mma_bf16(acc[mi][bj*2+0], al[mi], bh[0], bh[1]);
                    mma_bf16(acc[mi][bj*2+1], ah[mi], bh[2], bh[3]);
                    mma_bf16(acc[mi][bj*2+1], ah[mi], bl[2], bl[3]);
                    mma_bf16(acc[mi][bj*2+1], al[mi], bh[2], bh[3]);
                }
            }
        }
        __syncthreads();
    }

    const int qr = lane >> 2, qc = lane & 3;
    #pragma unroll
    for (int mi = 0; mi < 2; mi++) {
        int row0 = p0 + wm * 32 + mi * 16 + qr;
        float* r0 = g_val + ((size_t)bn * PP + row0) * DDIM;
        float* r1 = r0 + 8 * DDIM;
        #pragma unroll
        for (int nt = 0; nt < 8; nt++) {
            int col = wn * 64 + nt * 8 + qc * 2;
            *(float2*)(r0 + col) = make_float2(acc[mi][nt][0], acc[mi][nt][1]);
            *(float2*)(r1 + col) = make_float2(acc[mi][nt][2], acc[mi][nt][3]);
        }
    }
}

// ---------------------------------------------------------------------------
// K2: homography + bilinear sample + normalized dot + softmax + weighted sum
// ---------------------------------------------------------------------------
__global__ void __launch_bounds__(256) k2_attn()
{
    int b    = blockIdx.y;
    int p    = blockIdx.x * 8 + (threadIdx.x >> 5);
    int lane = threadIdx.x & 31;

    int col = p % WW, row = p / WW;
    float pxc = (float)col * (IMG_W / (float)(WW - 1));
    float pyc = (float)row * (IMG_H / (float)(HH - 1));

    const float4* qptr = (const float4*)(g_val + ((size_t)(b*NN + 0) * PP + p) * DDIM);
    float4 q4 = qptr[lane];
    float qss = wred(q4.x*q4.x + q4.y*q4.y + q4.z*q4.z + q4.w*q4.w);
    float qinv = 1.f / fmaxf(sqrtf(qss), 1e-12f);

    float4 s4[NN];
    float dotv[NN];

    #pragma unroll
    for (int n = 0; n < NN; n++) {
        const float* H = g_Hm + (b*NN + n) * 9;
        float hz = fmaf(H[6], pxc, fmaf(H[7], pyc, H[8]));
        float hx = fmaf(H[0], pxc, fmaf(H[1], pyc, H[2])) / hz;
        float hy = fmaf(H[3], pxc, fmaf(H[4], pyc, H[5])) / hz;
        float sx = hx * ((float)WW / IMG_W);
        float sy = hy * ((float)HH / IMG_H);
        bool valid = (sx >= 0.f) && (sx <= (float)(WW-1)) &&
                     (sy >= 0.f) && (sy <= (float)(HH-1));
        sx = fminf(fmaxf(sx, -1e4f), 1e4f);
        sy = fminf(fmaxf(sy, -1e4f), 1e4f);
        float x0f = floorf(sx), y0f = floorf(sy);
        int   x0 = (int)x0f,    y0 = (int)y0f;
        float fx = sx - x0f, fy = sy - y0f;

        float4 acc = make_float4(0.f, 0.f, 0.f, 0.f);
        const float* vb = g_val + (size_t)(b*NN + n) * PP * DDIM;
        #pragma unroll
        for (int c = 0; c < 4; c++) {
            int cx = x0 + (c & 1);
            int cy = y0 + (c >> 1);
            float wx = (c & 1)  ? fx : 1.f - fx;
            float wy = (c >> 1) ? fy : 1.f - fy;
            if (cx >= 0 && cx < WW && cy >= 0 && cy < HH) {
                const float4* vp = (const float4*)(vb + ((size_t)(cy*WW + cx)) * DDIM) + lane;
                float4 v = *vp;
                float w = wx * wy;
                acc.x = fmaf(w, v.x, acc.x);
                acc.y = fmaf(w, v.y, acc.y);
                acc.z = fmaf(w, v.z, acc.z);
                acc.w = fmaf(w, v.w, acc.w);
            }
        }
        s4[n] = acc;
        float ss = acc.x*acc.x + acc.y*acc.y + acc.z*acc.z + acc.w*acc.w;
        float dd = q4.x*acc.x + q4.y*acc.y + q4.z*acc.z + q4.w*acc.w;
        #pragma unroll
        for (int o = 16; o; o >>= 1) {
            ss += __shfl_xor_sync(0xffffffffu, ss, o);
            dd += __shfl_xor_sync(0xffffffffu, dd, o);
        }
        float sinv = 1.f / fmaxf(sqrtf(ss), 1e-12f);
        dotv[n] = valid ? dd * qinv * sinv : 0.f;
    }

    float m = dotv[0];
    #pragma unroll
    for (int n = 1; n < NN; n++) m = fmaxf(m, dotv[n]);
    float e[NN], se = 0.f;
    #pragma unroll
    for (int n = 0; n < NN; n++) { e[n] = expf(dotv[n] - m); se += e[n]; }
    float inv = 1.f / se;

    float4 o = q4;
    #pragma unroll
    for (int n = 0; n < NN; n++) {
        float a = e[n] * inv;
        o.x = fmaf(a, s4[n].x, o.x);
        o.y = fmaf(a, s4[n].y, o.y);
        o.z = fmaf(a, s4[n].z, o.z);
        o.w = fmaf(a, s4[n].w, o.w);
    }
    float4* zp = (float4*)(g_z + ((size_t)b * PP + p) * DDIM);
    zp[lane] = o;
}

// ---------------------------------------------------------------------------
// K3 (HMMA): LN1 -> GEMM1(64x256x128) -> gelu -> GEMM2(64x128x256)
//            -> residual(LN1 out) -> LN2 -> transposed store
// CTA = 64 pixels, 8 warps.
// smem: X tiles (2 k-chunks of [64][64] bf16 hi/lo), W tile region (reused,
// also out-stage), H tiles (4 k-chunks of [64][64] hi/lo).
// ---------------------------------------------------------------------------
#define S3_XHI 0          //  2 x 8192
#define S3_XLO 16384
#define S3_WHI 32768      // 32KB
#define S3_WLO 65536      // 32KB
#define S3_HHI 98304      //  4 x 8192
#define S3_HLO 131072
#define K3T_SMEM 163840
#define OS_STRIDE 132

__global__ void __launch_bounds__(256)
k3_mlp_tc(const float* __restrict__ l1g, const float* __restrict__ l1b,
          const float* __restrict__ b1v, const float* __restrict__ b2v,
          const float* __restrict__ l2g, const float* __restrict__ l2b,
          float* __restrict__ out)
{
    extern __shared__ char sm3[];
    const uint32_t sb = smem_u32(sm3);
    const int b  = blockIdx.y;
    const int p0 = blockIdx.x * 64;
    const int t  = threadIdx.x;
    const int lane = t & 31, wid = t >> 5;

    // ---- Phase 0: load z, LN1, write X hi/lo tiles ----
    {
        const float* zb = g_z + ((size_t)b * PP + p0) * DDIM;
        float4 g  = *(const float4*)(l1g + lane * 4);
        float4 be = *(const float4*)(l1b + lane * 4);
        #pragma unroll
        for (int rr = 0; rr < 8; rr++) {
            int row = wid * 8 + rr;
            float4 v = *(const float4*)(zb + (size_t)row * DDIM + lane * 4);
            float s  = wred(v.x + v.y + v.z + v.w);
            float s2 = wred(v.x*v.x + v.y*v.y + v.z*v.z + v.w*v.w);
            float mu = s * (1.f/128.f);
            float var = s2 * (1.f/128.f) - mu*mu;
            float rs = rsqrtf(var + 1e-5f);
            float x0 = (v.x - mu) * rs * g.x + be.x;
            float x1 = (v.y - mu) * rs * g.y + be.y;
            float x2 = (v.z - mu) * rs * g.z + be.z;
            float x3 = (v.w - mu) * rs * g.w + be.w;
            uint2 pA = split_pack(x0, x1);
            uint2 pB = split_pack(x2, x3);
            uint32_t base = (uint32_t)(lane >> 4) * 8192 + (uint32_t)row * 128;
            uint32_t o0 = base + ((((lane & 15) * 8) + 0) ^ ((row & 7) << 4));
            uint32_t o1 = base + ((((lane & 15) * 8) + 4) ^ ((row & 7) << 4));
            *(uint32_t*)(sm3 + S3_XHI + o0) = pA.x;
            *(uint32_t*)(sm3 + S3_XLO + o0) = pA.y;
            *(uint32_t*)(sm3 + S3_XHI + o1) = pB.x;
            *(uint32_t*)(sm3 + S3_XLO + o1) = pB.y;
        }
    }
    __syncthreads();

    const int wm = wid & 1;       // row half (32 rows)
    const int wn = wid >> 1;      // 0..3
    const int qr = lane >> 2, qc = lane & 3;

    // ---- GEMM1: H[64x256] = X[64x128] @ W1 ----
    float acc[2][8][4];
    #pragma unroll
    for (int mi = 0; mi < 2; mi++)
        #pragma unroll
        for (int nt = 0; nt < 8; nt++)
            #pragma unroll
            for (int j = 0; j < 4; j++) acc[mi][nt][j] = 0.f;

    for (int kc = 0; kc < 2; kc++) {
        // load W1^T chunk [256 n][32 kpairs]
        #pragma unroll 4
        for (int i = 0; i < 32; i++) {
            int idx = t + i * 256;
            int kpl = idx & 31, nl = idx >> 5;
            uint2 w = g_w1p[nl * 64 + kc * 32 + kpl];
            uint32_t off = (uint32_t)nl * 128 + (((uint32_t)kpl * 4) ^ ((nl & 7) << 4));
            *(uint32_t*)(sm3 + S3_WHI + off) = w.x;
            *(uint32_t*)(sm3 + S3_WLO + off) = w.y;
        }
        __syncthreads();

        #pragma unroll
        for (int ks = 0; ks < 4; ks++) {
            const uint32_t kb = (uint32_t)ks * 32;
            uint32_t ah[2][4], al[2][4];
            #pragma unroll
            for (int mi = 0; mi < 2; mi++) {
                uint32_t row = (uint32_t)(wm * 32 + mi * 16 + (lane & 15));
                uint32_t kby = kb + ((lane >> 4) << 4);
                uint32_t off = (uint32_t)kc * 8192 + row * 128 + (kby ^ ((row & 7) << 4));
                ldsm_x4(ah[mi], sb + S3_XHI + off);
                ldsm_x4(al[mi], sb + S3_XLO + off);
            }
            #pragma unroll
            for (int bj = 0; bj < 4; bj++) {
                uint32_t rown = (uint32_t)(wn * 64 + bj * 16 + (lane & 7) + ((lane >> 4) << 3));
                uint32_t kby  = kb + (((lane >> 3) & 1) << 4);
                uint32_t off  = rown * 128 + (kby ^ ((rown & 7) << 4));
                uint32_t bh[4], bl[4];
                ldsm_x4(bh, sb + S3_WHI + off);
                ldsm_x4(bl, sb + S3_WLO + off);
                #pragma unroll
                for (int mi = 0; mi < 2; mi++) {
                    mma_bf16(acc[mi][bj*2+0], ah[mi], bh[0], bh[1]);
                    mma_bf16(acc[mi][bj*2+0], ah[mi], bl[0], bl[1]);
                    mma_bf16(acc[mi][bj*2+0], al[mi], bh[0], bh[1]);
                    mma_bf16(acc[mi][bj*2+1], ah[mi], bh[2], bh[3]);
                    mma_bf16(acc[mi][bj*2+1], ah[mi], bl[2], bl[3]);
                    mma_bf16(acc[mi][bj*2+1], al[mi], bh[2], bh[3]);
                }
            }
        }
        __syncthreads();
    }

    // ---- gelu + write H tiles (chunk = wn) ----
    {
        #pragma unroll
        for (int mi = 0; mi < 2; mi++) {
            int R0 = wm * 32 + mi * 16 + qr;
            int R1 = R0 + 8;
            #pragma unroll
            for (int nt = 0; nt < 8; nt++) {
                int C = wn * 64 + nt * 8 + qc * 2;
                float h00 = geluf(acc[mi][nt][0] + b1v[C]);
                float h01 = geluf(acc[mi][nt][1] + b1v[C+1]);
                float h10 = geluf(acc[mi][nt][2] + b1v[C]);
                float h11 = geluf(acc[mi][nt][3] + b1v[C+1]);
                uint2 pA = split_pack(h00, h01);
                uint2 pB = split_pack(h10, h11);
                uint32_t base = (uint32_t)wn * 8192;
                uint32_t kloc = (uint32_t)(nt * 16 + qc * 4);
                uint32_t oA = base + (uint32_t)R0 * 128 + (kloc ^ ((R0 & 7) << 4));
                uint32_t oB = base + (uint32_t)R1 * 128 + (kloc ^ ((R1 & 7) << 4));
                *(uint32_t*)(sm3 + S3_HHI + oA) = pA.x;
                *(uint32_t*)(sm3 + S3_HLO + oA) = pA.y;
                *(uint32_t*)(sm3 + S3_HHI + oB) = pB.x;
                *(uint32_t*)(sm3 + S3_HLO + oB) = pB.y;
            }
        }
    }
    __syncthreads();

    // ---- GEMM2: O[64x128] = H[64x256] @ W2 ----
    float acc2[2][4][4];
    #pragma unroll
    for (int mi = 0; mi < 2; mi++)
        #pragma unroll
        for (int nt = 0; nt < 4; nt++)
            #pragma unroll
            for (int j = 0; j < 4; j++) acc2[mi][nt][j] = 0.f;

    for (int kc = 0; kc < 4; kc++) {
        // load W2^T chunk [128 n][32 kpairs]
        #pragma unroll 4
        for (int i = 0; i < 16; i++) {
            int idx = t + i * 256;
            int kpl = idx & 31, nl = idx >> 5;
            uint2 w = g_w2p[nl * 128 + kc * 32 + kpl];
            uint32_t off = (uint32_t)nl * 128 + (((uint32_t)kpl * 4) ^ ((nl & 7) << 4));
            *(uint32_t*)(sm3 + S3_WHI + off) = w.x;
            *(uint32_t*)(sm3 + S3_WLO + off) = w.y;
        }
        __syncthreads();

        #pragma unroll
        for (int ks = 0; ks < 4; ks++) {
            const uint32_t kb = (uint32_t)ks * 32;
            uint32_t ah[2][4], al[2][4];
            #pragma unroll
            for (int mi = 0; mi < 2; mi++) {
                uint32_t row = (uint32_t)(wm * 32 + mi * 16 + (lane & 15));
                uint32_t kby = kb + ((lane >> 4) << 4);
                uint32_t off = (uint32_t)kc * 8192 + row * 128 + (kby ^ ((row & 7) << 4));
                ldsm_x4(ah[mi], sb + S3_HHI + off);
                ldsm_x4(al[mi], sb + S3_HLO + off);
            }
            #pragma unroll
            for (int bj = 0; bj < 2; bj++) {
                uint32_t rown = (uint32_t)(wn * 32 + bj * 16 + (lane & 7) + ((lane >> 4) << 3));
                uint32_t kby  = kb + (((lane >> 3) & 1) << 4);
                uint32_t off  = rown * 128 + (kby ^ ((rown & 7) << 4));
                uint32_t bh[4], bl[4];
                ldsm_x4(bh, sb + S3_WHI + off);
                ldsm_x4(bl, sb + S3_WLO + off);
                #pragma unroll
                for (int mi = 0; mi < 2; mi++) {
                    mma_bf16(acc2[mi][bj*2+0], ah[mi], bh[0], bh[1]);
                    mma_bf16(acc2[mi][bj*2+0], ah[mi], bl[0], bl[1]);
                    mma_bf16(acc2[mi][bj*2+0], al[mi], bh[0], bh[1]);
                    mma_bf16(acc2[mi][bj*2+1], ah[mi], bh[2], bh[3]);
                    mma_bf16(acc2[mi][bj*2+1], ah[mi], bl[2], bl[3]);
                    mma_bf16(acc2[mi][bj*2+1], al[mi], bh[2], bh[3]);
                }
            }
        }
        __syncthreads();
    }

    // ---- epilogue: residual (= LN1 output, reconstructed hi+lo) + bias ----
    float* outstage = (float*)(sm3 + S3_WHI);   // [64][OS_STRIDE]
    {
        #pragma unroll
        for (int mi = 0; mi < 2; mi++) {
            #pragma unroll
            for (int nt = 0; nt < 4; nt++) {
                int C = wn * 32 + nt * 8 + qc * 2;
                float bC0 = b2v[C], bC1 = b2v[C+1];
                #pragma unroll
                for (int rh = 0; rh < 2; rh++) {
                    int R = wm * 32 + mi * 16 + qr + rh * 8;
                    uint32_t off = (uint32_t)(C >> 6) * 8192 + (uint32_t)R * 128 +
                                   ((((uint32_t)(C & 63)) * 2) ^ ((R & 7) << 4));
                    uint32_t xh = *(uint32_t*)(sm3 + S3_XHI + off);
                    uint32_t xl = *(uint32_t*)(sm3 + S3_XLO + off);
                    float r0 = bflo_f(xh) + bflo_f(xl);
                    float r1 = bfhi_f(xh) + bfhi_f(xl);
                    outstage[R * OS_STRIDE + C]     = r0 + acc2[mi][nt][rh*2+0] + bC0;
                    outstage[R * OS_STRIDE + C + 1] = r1 + acc2[mi][nt][rh*2+1] + bC1;
                }
            }
        }
    }
    __syncthreads();

    // ---- LN2 (warp: 8 rows) ----
    #pragma unroll
    for (int k = 0; k < 8; k++) {
        int pp = wid * 8 + k;
        float v0 = outstage[pp*OS_STRIDE + lane];
        float v1 = outstage[pp*OS_STRIDE + lane + 32];
        float v2 = outstage[pp*OS_STRIDE + lane + 64];
        float v3 = outstage[pp*OS_STRIDE + lane + 96];
        float s  = wred(v0+v1+v2+v3);
        float s2 = wred(v0*v0+v1*v1+v2*v2+v3*v3);
        float mu = s * (1.f/128.f);
        float var = s2 * (1.f/128.f) - mu*mu;
        float rs = rsqrtf(var + 1e-5f);
        outstage[pp*OS_STRIDE + lane]      = (v0-mu)*rs*l2g[lane]    + l2b[lane];
        outstage[pp*OS_STRIDE + lane + 32] = (v1-mu)*rs*l2g[lane+32] + l2b[lane+32];
        outstage[pp*OS_STRIDE + lane + 64] = (v2-mu)*rs*l2g[lane+64] + l2b[lane+64];
        outstage[pp*OS_STRIDE + lane + 96] = (v3-mu)*rs*l2g[lane+96] + l2b[lane+96];
    }
    __syncthreads();

    // ---- transposed store: out[b][d][p0..p0+63] ----
    for (int i = t; i < 64 * DDIM; i += 256) {
        int d = i >> 6, pp = i & 63;
        out[((size_t)b * DDIM + d) * PP + p0 + pp] = outstage[pp * OS_STRIDE + d];
    }
}

// ---------------------------------------------------------------------------
extern "C" void kernel_launch(void* const* d_in, const int* in_sizes, int n_in,
                              void* d_out, int out_size)
{
    const float* feature   = (const float*)d_in[0];
    const float* I_src     = (const float*)d_in[1];
    const float* I_tar_inv = (const float*)d_in[2];
    const float* E         = (const float*)d_in[3];
    const float* dis       = (const float*)d_in[4];
    const float* norm_vec  = (const float*)d_in[5];
    const float* bn_gamma  = (const float*)d_in[6];
    const float* bn_beta   = (const float*)d_in[7];
    const float* bn_mean   = (const float*)d_in[8];
    const float* bn_var    = (const float*)d_in[9];
    const float* conv_w    = (const float*)d_in[10];
    const float* ln1_g     = (const float*)d_in[11];
    const float* ln1_b     = (const float*)d_in[12];
    const float* mlp_w1    = (const float*)d_in[13];
    const float* mlp_b1    = (const float*)d_in[14];
    const float* mlp_w2    = (const float*)d_in[15];
    const float* mlp_b2    = (const float*)d_in[16];
    const float* ln2_g     = (const float*)d_in[17];
    const float* ln2_b     = (const float*)d_in[18];
    float* out = (float*)d_out;

    cudaFuncSetAttribute(k1_conv_tc,
                         cudaFuncAttributeMaxDynamicSharedMemorySize, K1_SMEM);
    cudaFuncSetAttribute(k3_mlp_tc,
                         cudaFuncAttributeMaxDynamicSharedMemorySize, K3T_SMEM);

    k0_prep<<<1, 256>>>(I_src, I_tar_inv, E, dis, norm_vec,
                        bn_gamma, bn_beta, bn_mean, bn_var);
    k0b_pack<<<64, 256>>>(conv_w, mlp_w1, mlp_w2);
    k1_conv_tc<<<dim3(PP/128, BN), 256, K1_SMEM>>>(feature);
    k2_attn<<<dim3(PP/8, BB), 256>>>();
    k3_mlp_tc<<<dim3(PP/64, BB), 256, K3T_SMEM>>>(ln1_g, ln1_b, mlp_b1, mlp_b2,
                                                  ln2_g, ln2_b, out);
}

// round 10
// speedup vs baseline: 2.2994x; 1.0869x over previous
#include <cuda_runtime.h>
#include <cuda_bf16.h>
#include <math.h>
#include <stdint.h>

// Problem constants
#define BB 4
#define NN 6
#define FDIM 256
#define DDIM 128
#define HH 64
#define WW 120
#define PP (HH*WW)          // 7680
#define BN (BB*NN)          // 24
#define IMG_H 480.0f
#define IMG_W 960.0f

// Scratch (device globals — no runtime allocation allowed)
__device__ float g_val[(size_t)BN * PP * DDIM];   // (bn, p, d)  94.4 MB
__device__ float g_z[(size_t)BB * PP * DDIM];     // (b, p, d)   15.7 MB
__device__ float g_Hm[BN * 9];
__device__ float g_bnscale[FDIM];
__device__ float g_bnshift[FDIM];
// Prepacked split-bf16 weights
__device__ uint32_t g_wch[128 * 128];  // conv_w hi pairs [d][kpair]
__device__ uint32_t g_wcl[128 * 128];  // conv_w lo pairs
__device__ uint2 g_w1p[256 * 64];      // W1^T  [n=256][kpair=64]
__device__ uint2 g_w2p[128 * 128];     // W2^T  [n=128][kpair=128]

// ===========================================================================
// helpers: sm_80-baseline tensor path (ldmatrix + mma.sync) — no 'a' features
// ===========================================================================
__device__ __forceinline__ uint32_t smem_u32(const void* p) {
    uint32_t a;
    asm("{ .reg .u64 t; cvta.to.shared.u64 t, %1; cvt.u32.u64 %0, t; }"
        : "=r"(a) : "l"(p));
    return a;
}
__device__ __forceinline__ void ldsm_x4(uint32_t* r, uint32_t addr) {
    asm volatile("ldmatrix.sync.aligned.m8n8.x4.shared.b16 {%0,%1,%2,%3}, [%4];"
        : "=r"(r[0]), "=r"(r[1]), "=r"(r[2]), "=r"(r[3]) : "r"(addr));
}
__device__ __forceinline__ void mma_bf16(float* c, const uint32_t* a,
                                         uint32_t b0, uint32_t b1) {
    asm volatile(
        "mma.sync.aligned.m16n8k16.row.col.f32.bf16.bf16.f32 "
        "{%0,%1,%2,%3}, {%4,%5,%6,%7}, {%8,%9}, {%0,%1,%2,%3};"
        : "+f"(c[0]), "+f"(c[1]), "+f"(c[2]), "+f"(c[3])
        : "r"(a[0]), "r"(a[1]), "r"(a[2]), "r"(a[3]), "r"(b0), "r"(b1));
}
__device__ __forceinline__ void cp_async16(uint32_t smem_addr, const void* gptr) {
    asm volatile("cp.async.ca.shared.global [%0], [%1], 16;"
        :: "r"(smem_addr), "l"(gptr) : "memory");
}
__device__ __forceinline__ uint32_t pack_bf16x2(__nv_bfloat16 lo, __nv_bfloat16 hi) {
    return ((uint32_t)__bfloat16_as_ushort(hi) << 16) | __bfloat16_as_ushort(lo);
}
__device__ __forceinline__ uint2 split_pack(float a, float b) {
    __nv_bfloat16 ha = __float2bfloat16(a), hb = __float2bfloat16(b);
    __nv_bfloat16 la = __float2bfloat16(a - __bfloat162float(ha));
    __nv_bfloat16 lb = __float2bfloat16(b - __bfloat162float(hb));
    return make_uint2(pack_bf16x2(ha, hb), pack_bf16x2(la, lb));
}
__device__ __forceinline__ float bflo_f(uint32_t u) { return __uint_as_float(u << 16); }
__device__ __forceinline__ float bfhi_f(uint32_t u) { return __uint_as_float(u & 0xffff0000u); }
__device__ __forceinline__ float geluf(float h) {
    return 0.5f * h * (1.f + erff(h * 0.70710678118654752f));
}
__device__ __forceinline__ float wred(float v) {
    #pragma unroll
    for (int o = 16; o; o >>= 1) v += __shfl_xor_sync(0xffffffffu, v, o);
    return v;
}

// ---------------------------------------------------------------------------
// K0: homographies + BN scale/shift
// ---------------------------------------------------------------------------
__global__ void k0_prep(const float* __restrict__ I_src,
                        const float* __restrict__ I_tar_inv,
                        const float* __restrict__ E,
                        const float* __restrict__ disp,
                        const float* __restrict__ nvec,
                        const float* __restrict__ bng,
                        const float* __restrict__ bnb,
                        const float* __restrict__ bnm,
                        const float* __restrict__ bnv)
{
    int t = threadIdx.x;
    if (t < FDIM) {
        float sc = bng[t] * rsqrtf(bnv[t] + 1e-5f);
        g_bnscale[t] = sc;
        g_bnshift[t] = bnb[t] - bnm[t] * sc;
    }
    if (t < BN) {
        int b = t / NN;
        float dis = disp[0];
        const float* Eb = E + t * 16;
        const float* Ks = I_src + t * 9;
        const float* Kt = I_tar_inv + b * 9;
        float nv0 = nvec[b*3+0], nv1 = nvec[b*3+1], nv2 = nvec[b*3+2];
        float A[9];
        #pragma unroll
        for (int i = 0; i < 3; i++) {
            float Ti = Eb[i*4+3] / dis;
            A[i*3+0] = Eb[i*4+0] - Ti * nv0;
            A[i*3+1] = Eb[i*4+1] - Ti * nv1;
            A[i*3+2] = Eb[i*4+2] - Ti * nv2;
        }
        float M[9];
        #pragma unroll
        for (int i = 0; i < 3; i++)
            #pragma unroll
            for (int j = 0; j < 3; j++)
                M[i*3+j] = Ks[i*3+0]*A[0*3+j] + Ks[i*3+1]*A[1*3+j] + Ks[i*3+2]*A[2*3+j];
        #pragma unroll
        for (int i = 0; i < 3; i++)
            #pragma unroll
            for (int j = 0; j < 3; j++)
                g_Hm[t*9 + i*3+j] = M[i*3+0]*Kt[0*3+j] + M[i*3+1]*Kt[1*3+j] + M[i*3+2]*Kt[2*3+j];
    }
}

// ---------------------------------------------------------------------------
// K0b: pack weights to split-bf16 transposed layouts
// ---------------------------------------------------------------------------
__global__ void k0b_pack(const float* __restrict__ Wc,
                         const float* __restrict__ W1,
                         const float* __restrict__ W2)
{
    int i = blockIdx.x * 256 + threadIdx.x;   // 0..16383
    {   // conv_w [128 d][256 f] -> split hi/lo pair arrays
        int d = i >> 7, fp = i & 127;
        uint2 p = split_pack(Wc[d*256 + fp*2], Wc[d*256 + fp*2 + 1]);
        g_wch[i] = p.x;
        g_wcl[i] = p.y;
    }
    {   // W2^T: g_w2p[n=d][kpair over j], W2 is [256 j][128 d]
        int d = i >> 7, kp = i & 127;
        g_w2p[i] = split_pack(W2[(kp*2)*128 + d], W2[(kp*2+1)*128 + d]);
    }
    {   // W1^T: g_w1p[n=j][kpair over d], W1 is [128 d][256 j]
        int j = i >> 6, kp = i & 63;
        g_w1p[i] = split_pack(W1[(kp*2)*256 + j], W1[(kp*2+1)*256 + j]);
    }
}

// ---------------------------------------------------------------------------
// K1 (HMMA, 2-stage pipelined): val[bn][p][d] = sum_f W[d][f]*relu(bn(feat))
// CTA tile 128px(M) x 128d(N), K-chunks of 64, double-buffered smem (128 KB).
// W via cp.async from prepacked hi/lo arrays; X prefetched to regs.
// ---------------------------------------------------------------------------
// stage s: X hi @ s*32768, X lo @ s*32768+16384; W hi @ 65536+s*32768, lo +16384
#define K1_SMEM 131072

__global__ void __launch_bounds__(256)
k1_conv_tc(const float* __restrict__ feat)
{
    extern __shared__ char smem[];
    const uint32_t sb = smem_u32(smem);
    const int bn = blockIdx.y;
    const int p0 = blockIdx.x * 128;
    const int t  = threadIdx.x;
    const int wid = t >> 5, lane = t & 31;
    const int wm = wid & 3;    // M quarter
    const int wn = wid >> 2;   // N half
    const int pl  = t & 127;   // this thread's pixel row (X producer)
    const int fp0 = t >> 7;    // kpair phase 0/1

    float acc[2][8][4];
    #pragma unroll
    for (int mi = 0; mi < 2; mi++)
        #pragma unroll
        for (int nt = 0; nt < 8; nt++)
            #pragma unroll
            for (int j = 0; j < 4; j++) acc[mi][nt][j] = 0.f;

    const float* fb = feat + (size_t)bn * FDIM * PP + p0;

    // ---- prologue: stage 0 = chunk 0 ----
    #pragma unroll
    for (int i = 0; i < 4; i++) {           // W chunk 0 via cp.async
        int idx = t + i * 256;              // 16B-unit 0..1023
        int kq = idx & 7, dl = idx >> 3;
        uint32_t off = (uint32_t)dl * 128 + (((uint32_t)kq * 16) ^ ((dl & 7) << 4));
        cp_async16(sb + 65536 + off,          g_wch + dl * 128 + kq * 4);
        cp_async16(sb + 65536 + 16384 + off,  g_wcl + dl * 128 + kq * 4);
    }
    asm volatile("cp.async.commit_group;" ::: "memory");
    #pragma unroll
    for (int i = 0; i < 16; i++) {          // X chunk 0 direct
        int fp = fp0 + 2 * i;               // kpair 0..31
        int f  = 2 * fp;
        float v0 = fb[(size_t)f       * PP + pl];
        float v1 = fb[(size_t)(f + 1) * PP + pl];
        v0 = fmaxf(fmaf(v0, g_bnscale[f],   g_bnshift[f]),   0.f);
        v1 = fmaxf(fmaf(v1, g_bnscale[f+1], g_bnshift[f+1]), 0.f);
        uint2 p = split_pack(v0, v1);
        uint32_t off = (uint32_t)pl * 128 + (((uint32_t)fp * 4) ^ ((pl & 7) << 4));
        *(uint32_t*)(smem + off)         = p.x;
        *(uint32_t*)(smem + 16384 + off) = p.y;
    }

    for (int c = 0; c < 4; c++) {
        const int s = c & 1;
        const uint32_t xbase = sb + (uint32_t)s * 32768;
        const uint32_t wbase = sb + 65536 + (uint32_t)s * 32768;

        // prefetch next chunk's X into registers (latency hidden by MMAs)
        float v0r[16], v1r[16];
        if (c < 3) {
            const int f0n = (c + 1) * 64;
            #pragma unroll
            for (int i = 0; i < 16; i++) {
                int f = f0n + 2 * (fp0 + 2 * i);
                v0r[i] = fb[(size_t)f       * PP + pl];
                v1r[i] = fb[(size_t)(f + 1) * PP + pl];
            }
        }

        asm volatile("cp.async.wait_group 0;" ::: "memory");
        __syncthreads();   // stage s fully ready; stage s^1 free

        // issue W cp.async for chunk c+1 into stage s^1 (overlaps MMAs)
        if (c < 3) {
            #pragma unroll
            for (int i = 0; i < 4; i++) {
                int idx = t + i * 256;
                int kq = idx & 7, dl = idx >> 3;
                uint32_t off = (uint32_t)dl * 128 + (((uint32_t)kq * 16) ^ ((dl & 7) << 4));
                const uint32_t wb1 = sb + 65536 + (uint32_t)(s ^ 1) * 32768;
                cp_async16(wb1 + off,         g_wch + dl * 128 + (c + 1) * 32 + kq * 4);
                cp_async16(wb1 + 16384 + off, g_wcl + dl * 128 + (c + 1) * 32 + kq * 4);
            }
            asm volatile("cp.async.commit_group;" ::: "memory");
        }

        // ---- MMAs on stage s ----
        #pragma unroll
        for (int ks = 0; ks < 4; ks++) {
            const uint32_t kb = (uint32_t)ks * 32;
            uint32_t ah[2][4], al[2][4];
            #pragma unroll
            for (int mi = 0; mi < 2; mi++) {
                uint32_t row = (uint32_t)(wm * 32 + mi * 16 + (lane & 15));
                uint32_t kby = kb + ((lane >> 4) << 4);
                uint32_t off = row * 128 + (kby ^ ((row & 7) << 4));
                ldsm_x4(ah[mi], xbase + off);
                ldsm_x4(al[mi], xbase + 16384 + off);
            }
            #pragma unroll
            for (int bj = 0; bj < 4; bj++) {
                uint32_t rown = (uint32_t)(wn * 64 + bj * 16 + (lane & 7) + ((lane >> 4) << 3));
                uint32_t kby  = kb + (((lane >> 3) & 1) << 4);
                uint32_t off  = rown * 128 + (kby ^ ((rown & 7) << 4));
                uint32_t bh[4], bl[4];
                ldsm_x4(bh, wbase + off);
                ldsm_x4(bl, wbase + 16384 + off);
                #pragma unroll
                for (int mi = 0; mi < 2; mi++) {
                    mma_bf16(acc[mi][bj*2+0], ah[mi], bh[0], bh[1]);
                    mma_bf16(acc[mi][bj*2+0], ah[mi], bl[0], bl[1]);
                    mma_bf16(acc[mi][bj*2+0], al[mi], bh[0], bh[1]);
                    mma_bf16(acc[mi][bj*2+1], ah[mi], bh[2], bh[3]);
                    mma_bf16(acc[mi][bj*2+1], ah[mi], bl[2], bl[3]);
                    mma_bf16(acc[mi][bj*2+1], al[mi], bh[2], bh[3]);
                }
            }
        }

        // ---- convert prefetched X -> stage s^1 ----
        if (c < 3) {
            const int f0n = (c + 1) * 64;
            char* xdst = smem + (size_t)(s ^ 1) * 32768;
            #pragma unroll
            for (int i = 0; i < 16; i++) {
                int fp = fp0 + 2 * i;
                int f  = f0n + 2 * fp;
                float v0 = fmaxf(fmaf(v0r[i], g_bnscale[f],   g_bnshift[f]),   0.f);
                float v1 = fmaxf(fmaf(v1r[i], g_bnscale[f+1], g_bnshift[f+1]), 0.f);
                uint2 p = split_pack(v0, v1);
                uint32_t off = (uint32_t)pl * 128 + (((uint32_t)fp * 4) ^ ((pl & 7) << 4));
                *(uint32_t*)(xdst + off)         = p.x;
                *(uint32_t*)(xdst + 16384 + off) = p.y;
            }
        }
    }

    const int qr = lane >> 2, qc = lane & 3;
    #pragma unroll
    for (int mi = 0; mi < 2; mi++) {
        int row0 = p0 + wm * 32 + mi * 16 + qr;
        float* r0 = g_val + ((size_t)bn * PP + row0) * DDIM;
        float* r1 = r0 + 8 * DDIM;
        #pragma unroll
        for (int nt = 0; nt < 8; nt++) {
            int col = wn * 64 + nt * 8 + qc * 2;
            *(float2*)(r0 + col) = make_float2(acc[mi][nt][0], acc[mi][nt][1]);
            *(float2*)(r1 + col) = make_float2(acc[mi][nt][2], acc[mi][nt][3]);
        }
    }
}

// ---------------------------------------------------------------------------
// K2: homography + bilinear sample + normalized dot + softmax + weighted sum
// ---------------------------------------------------------------------------
__global__ void __launch_bounds__(256) k2_attn()
{
    int b    = blockIdx.y;
    int p    = blockIdx.x * 8 + (threadIdx.x >> 5);
    int lane = threadIdx.x & 31;

    int col = p % WW, row = p / WW;
    float pxc = (float)col * (IMG_W / (float)(WW - 1));
    float pyc = (float)row * (IMG_H / (float)(HH - 1));

    const float4* qptr = (const float4*)(g_val + ((size_t)(b*NN + 0) * PP + p) * DDIM);
    float4 q4 = qptr[lane];
    float qss = wred(q4.x*q4.x + q4.y*q4.y + q4.z*q4.z + q4.w*q4.w);
    float qinv = 1.f / fmaxf(sqrtf(qss), 1e-12f);

    float4 s4[NN];
    float dotv[NN];

    #pragma unroll
    for (int n = 0; n < NN; n++) {
        const float* H = g_Hm + (b*NN + n) * 9;
        float hz = fmaf(H[6], pxc, fmaf(H[7], pyc, H[8]));
        float hx = fmaf(H[0], pxc, fmaf(H[1], pyc, H[2])) / hz;
        float hy = fmaf(H[3], pxc, fmaf(H[4], pyc, H[5])) / hz;
        float sx = hx * ((float)WW / IMG_W);
        float sy = hy * ((float)HH / IMG_H);
        bool valid = (sx >= 0.f) && (sx <= (float)(WW-1)) &&
                     (sy >= 0.f) && (sy <= (float)(HH-1));
        sx = fminf(fmaxf(sx, -1e4f), 1e4f);
        sy = fminf(fmaxf(sy, -1e4f), 1e4f);
        float x0f = floorf(sx), y0f = floorf(sy);
        int   x0 = (int)x0f,    y0 = (int)y0f;
        float fx = sx - x0f, fy = sy - y0f;

        float4 acc = make_float4(0.f, 0.f, 0.f, 0.f);
        const float* vb = g_val + (size_t)(b*NN + n) * PP * DDIM;
        #pragma unroll
        for (int c = 0; c < 4; c++) {
            int cx = x0 + (c & 1);
            int cy = y0 + (c >> 1);
            float wx = (c & 1)  ? fx : 1.f - fx;
            float wy = (c >> 1) ? fy : 1.f - fy;
            if (cx >= 0 && cx < WW && cy >= 0 && cy < HH) {
                const float4* vp = (const float4*)(vb + ((size_t)(cy*WW + cx)) * DDIM) + lane;
                float4 v = *vp;
                float w = wx * wy;
                acc.x = fmaf(w, v.x, acc.x);
                acc.y = fmaf(w, v.y, acc.y);
                acc.z = fmaf(w, v.z, acc.z);
                acc.w = fmaf(w, v.w, acc.w);
            }
        }
        s4[n] = acc;
        float ss = acc.x*acc.x + acc.y*acc.y + acc.z*acc.z + acc.w*acc.w;
        float dd = q4.x*acc.x + q4.y*acc.y + q4.z*acc.z + q4.w*acc.w;
        #pragma unroll
        for (int o = 16; o; o >>= 1) {
            ss += __shfl_xor_sync(0xffffffffu, ss, o);
            dd += __shfl_xor_sync(0xffffffffu, dd, o);
        }
        float sinv = 1.f / fmaxf(sqrtf(ss), 1e-12f);
        dotv[n] = valid ? dd * qinv * sinv : 0.f;
    }

    float m = dotv[0];
    #pragma unroll
    for (int n = 1; n < NN; n++) m = fmaxf(m, dotv[n]);
    float e[NN], se = 0.f;
    #pragma unroll
    for (int n = 0; n < NN; n++) { e[n] = expf(dotv[n] - m); se += e[n]; }
    float inv = 1.f / se;

    float4 o = q4;
    #pragma unroll
    for (int n = 0; n < NN; n++) {
        float a = e[n] * inv;
        o.x = fmaf(a, s4[n].x, o.x);
        o.y = fmaf(a, s4[n].y, o.y);
        o.z = fmaf(a, s4[n].z, o.z);
        o.w = fmaf(a, s4[n].w, o.w);
    }
    float4* zp = (float4*)(g_z + ((size_t)b * PP + p) * DDIM);
    zp[lane] = o;
}

// ---------------------------------------------------------------------------
// K3 (HMMA): LN1 -> GEMM1(64x256x128) -> gelu -> GEMM2(64x128x256)
//            -> residual(LN1 out) -> LN2 -> transposed store
// ---------------------------------------------------------------------------
#define S3_XHI 0
#define S3_XLO 16384
#define S3_WHI 32768
#define S3_WLO 65536
#define S3_HHI 98304
#define S3_HLO 131072
#define K3T_SMEM 163840
#define OS_STRIDE 132

__global__ void __launch_bounds__(256)
k3_mlp_tc(const float* __restrict__ l1g, const float* __restrict__ l1b,
          const float* __restrict__ b1v, const float* __restrict__ b2v,
          const float* __restrict__ l2g, const float* __restrict__ l2b,
          float* __restrict__ out)
{
    extern __shared__ char sm3[];
    const uint32_t sb = smem_u32(sm3);
    const int b  = blockIdx.y;
    const int p0 = blockIdx.x * 64;
    const int t  = threadIdx.x;
    const int lane = t & 31, wid = t >> 5;

    // ---- Phase 0: load z, LN1, write X hi/lo tiles ----
    {
        const float* zb = g_z + ((size_t)b * PP + p0) * DDIM;
        float4 g  = *(const float4*)(l1g + lane * 4);
        float4 be = *(const float4*)(l1b + lane * 4);
        #pragma unroll
        for (int rr = 0; rr < 8; rr++) {
            int row = wid * 8 + rr;
            float4 v = *(const float4*)(zb + (size_t)row * DDIM + lane * 4);
            float s  = wred(v.x + v.y + v.z + v.w);
            float s2 = wred(v.x*v.x + v.y*v.y + v.z*v.z + v.w*v.w);
            float mu = s * (1.f/128.f);
            float var = s2 * (1.f/128.f) - mu*mu;
            float rs = rsqrtf(var + 1e-5f);
            float x0 = (v.x - mu) * rs * g.x + be.x;
            float x1 = (v.y - mu) * rs * g.y + be.y;
            float x2 = (v.z - mu) * rs * g.z + be.z;
            float x3 = (v.w - mu) * rs * g.w + be.w;
            uint2 pA = split_pack(x0, x1);
            uint2 pB = split_pack(x2, x3);
            uint32_t base = (uint32_t)(lane >> 4) * 8192 + (uint32_t)row * 128;
            uint32_t o0 = base + ((((lane & 15) * 8) + 0) ^ ((row & 7) << 4));
            uint32_t o1 = base + ((((lane & 15) * 8) + 4) ^ ((row & 7) << 4));
            *(uint32_t*)(sm3 + S3_XHI + o0) = pA.x;
            *(uint32_t*)(sm3 + S3_XLO + o0) = pA.y;
            *(uint32_t*)(sm3 + S3_XHI + o1) = pB.x;
            *(uint32_t*)(sm3 + S3_XLO + o1) = pB.y;
        }
    }
    __syncthreads();

    const int wm = wid & 1;
    const int wn = wid >> 1;
    const int qr = lane >> 2, qc = lane & 3;

    // ---- GEMM1: H[64x256] = X[64x128] @ W1 ----
    float acc[2][8][4];
    #pragma unroll
    for (int mi = 0; mi < 2; mi++)
        #pragma unroll
        for (int nt = 0; nt < 8; nt++)
            #pragma unroll
            for (int j = 0; j < 4; j++) acc[mi][nt][j] = 0.f;

    for (int kc = 0; kc < 2; kc++) {
        #pragma unroll 4
        for (int i = 0; i < 32; i++) {
            int idx = t + i * 256;
            int kpl = idx & 31, nl = idx >> 5;
            uint2 w = g_w1p[nl * 64 + kc * 32 + kpl];
            uint32_t off = (uint32_t)nl * 128 + (((uint32_t)kpl * 4) ^ ((nl & 7) << 4));
            *(uint32_t*)(sm3 + S3_WHI + off) = w.x;
            *(uint32_t*)(sm3 + S3_WLO + off) = w.y;
        }
        __syncthreads();

        #pragma unroll
        for (int ks = 0; ks < 4; ks++) {
            const uint32_t kb = (uint32_t)ks * 32;
            uint32_t ah[2][4], al[2][4];
            #pragma unroll
            for (int mi = 0; mi < 2; mi++) {
                uint32_t row = (uint32_t)(wm * 32 + mi * 16 + (lane & 15));
                uint32_t kby = kb + ((lane >> 4) << 4);
                uint32_t off = (uint32_t)kc * 8192 + row * 128 + (kby ^ ((row & 7) << 4));
                ldsm_x4(ah[mi], sb + S3_XHI + off);
                ldsm_x4(al[mi], sb + S3_XLO + off);
            }
            #pragma unroll
            for (int bj = 0; bj < 4; bj++) {
                uint32_t rown = (uint32_t)(wn * 64 + bj * 16 + (lane & 7) + ((lane >> 4) << 3));
                uint32_t kby  = kb + (((lane >> 3) & 1) << 4);
                uint32_t off  = rown * 128 + (kby ^ ((rown & 7) << 4));
                uint32_t bh[4], bl[4];
                ldsm_x4(bh, sb + S3_WHI + off);
                ldsm_x4(bl, sb + S3_WLO + off);
                #pragma unroll
                for (int mi = 0; mi < 2; mi++) {
                    mma_bf16(acc[mi][bj*2+0], ah[mi], bh[0], bh[1]);
                    mma_bf16(acc[mi][bj*2+0], ah[mi], bl[0], bl[1]);
                    mma_bf16(acc[mi][bj*2+0], al[mi], bh[0], bh[1]);
                    mma_bf16(acc[mi][bj*2+1], ah[mi], bh[2], bh[3]);
                    mma_bf16(acc[mi][bj*2+1], ah[mi], bl[2], bl[3]);
                    mma_bf16(acc[mi][bj*2+1], al[mi], bh[2], bh[3]);
                }
            }
        }
        __syncthreads();
    }

    // ---- gelu + write H tiles (chunk = wn) ----
    {
        #pragma unroll
        for (int mi = 0; mi < 2; mi++) {
            int R0 = wm * 32 + mi * 16 + qr;
            int R1 = R0 + 8;
            #pragma unroll
            for (int nt = 0; nt < 8; nt++) {
                int C = wn * 64 + nt * 8 + qc * 2;
                float h00 = geluf(acc[mi][nt][0] + b1v[C]);
                float h01 = geluf(acc[mi][nt][1] + b1v[C+1]);
                float h10 = geluf(acc[mi][nt][2] + b1v[C]);
                float h11 = geluf(acc[mi][nt][3] + b1v[C+1]);
                uint2 pA = split_pack(h00, h01);
                uint2 pB = split_pack(h10, h11);
                uint32_t base = (uint32_t)wn * 8192;
                uint32_t kloc = (uint32_t)(nt * 16 + qc * 4);
                uint32_t oA = base + (uint32_t)R0 * 128 + (kloc ^ ((R0 & 7) << 4));
                uint32_t oB = base + (uint32_t)R1 * 128 + (kloc ^ ((R1 & 7) << 4));
                *(uint32_t*)(sm3 + S3_HHI + oA) = pA.x;
                *(uint32_t*)(sm3 + S3_HLO + oA) = pA.y;
                *(uint32_t*)(sm3 + S3_HHI + oB) = pB.x;
                *(uint32_t*)(sm3 + S3_HLO + oB) = pB.y;
            }
        }
    }
    __syncthreads();

    // ---- GEMM2: O[64x128] = H[64x256] @ W2 ----
    float acc2[2][4][4];
    #pragma unroll
    for (int mi = 0; mi < 2; mi++)
        #pragma unroll
        for (int nt = 0; nt < 4; nt++)
            #pragma unroll
            for (int j = 0; j < 4; j++) acc2[mi][nt][j] = 0.f;

    for (int kc = 0; kc < 4; kc++) {
        #pragma unroll 4
        for (int i = 0; i < 16; i++) {
            int idx = t + i * 256;
            int kpl = idx & 31, nl = idx >> 5;
            uint2 w = g_w2p[nl * 128 + kc * 32 + kpl];
            uint32_t off = (uint32_t)nl * 128 + (((uint32_t)kpl * 4) ^ ((nl & 7) << 4));
            *(uint32_t*)(sm3 + S3_WHI + off) = w.x;
            *(uint32_t*)(sm3 + S3_WLO + off) = w.y;
        }
        __syncthreads();

        #pragma unroll
        for (int ks = 0; ks < 4; ks++) {
            const uint32_t kb = (uint32_t)ks * 32;
            uint32_t ah[2][4], al[2][4];
            #pragma unroll
            for (int mi = 0; mi < 2; mi++) {
                uint32_t row = (uint32_t)(wm * 32 + mi * 16 + (lane & 15));
                uint32_t kby = kb + ((lane >> 4) << 4);
                uint32_t off = (uint32_t)kc * 8192 + row * 128 + (kby ^ ((row & 7) << 4));
                ldsm_x4(ah[mi], sb + S3_HHI + off);
                ldsm_x4(al[mi], sb + S3_HLO + off);
            }
            #pragma unroll
            for (int bj = 0; bj < 2; bj++) {
                uint32_t rown = (uint32_t)(wn * 32 + bj * 16 + (lane & 7) + ((lane >> 4) << 3));
                uint32_t kby  = kb + (((lane >> 3) & 1) << 4);
                uint32_t off  = rown * 128 + (kby ^ ((rown & 7) << 4));
                uint32_t bh[4], bl[4];
                ldsm_x4(bh, sb + S3_WHI + off);
                ldsm_x4(bl, sb + S3_WLO + off);
                #pragma unroll
                for (int mi = 0; mi < 2; mi++) {
                    mma_bf16(acc2[mi][bj*2+0], ah[mi], bh[0], bh[1]);
                    mma_bf16(acc2[mi][bj*2+0], ah[mi], bl[0], bl[1]);
                    mma_bf16(acc2[mi][bj*2+0], al[mi], bh[0], bh[1]);
                    mma_bf16(acc2[mi][bj*2+1], ah[mi], bh[2], bh[3]);
                    mma_bf16(acc2[mi][bj*2+1], ah[mi], bl[2], bl[3]);
                    mma_bf16(acc2[mi][bj*2+1], al[mi], bh[2], bh[3]);
                }
            }
        }
        __syncthreads();
    }

    // ---- epilogue: residual + bias ----
    float* outstage = (float*)(sm3 + S3_WHI);
    {
        #pragma unroll
        for (int mi = 0; mi < 2; mi++) {
            #pragma unroll
            for (int nt = 0; nt < 4; nt++) {
                int C = wn * 32 + nt * 8 + qc * 2;
                float bC0 = b2v[C], bC1 = b2v[C+1];
                #pragma unroll
                for (int rh = 0; rh < 2; rh++) {
                    int R = wm * 32 + mi * 16 + qr + rh * 8;
                    uint32_t off = (uint32_t)(C >> 6) * 8192 + (uint32_t)R * 128 +
                                   ((((uint32_t)(C & 63)) * 2) ^ ((R & 7) << 4));
                    uint32_t xh = *(uint32_t*)(sm3 + S3_XHI + off);
                    uint32_t xl = *(uint32_t*)(sm3 + S3_XLO + off);
                    float r0 = bflo_f(xh) + bflo_f(xl);
                    float r1 = bfhi_f(xh) + bfhi_f(xl);
                    outstage[R * OS_STRIDE + C]     = r0 + acc2[mi][nt][rh*2+0] + bC0;
                    outstage[R * OS_STRIDE + C + 1] = r1 + acc2[mi][nt][rh*2+1] + bC1;
                }
            }
        }
    }
    __syncthreads();

    // ---- LN2 ----
    #pragma unroll
    for (int k = 0; k < 8; k++) {
        int pp = wid * 8 + k;
        float v0 = outstage[pp*OS_STRIDE + lane];
        float v1 = outstage[pp*OS_STRIDE + lane + 32];
        float v2 = outstage[pp*OS_STRIDE + lane + 64];
        float v3 = outstage[pp*OS_STRIDE + lane + 96];
        float s  = wred(v0+v1+v2+v3);
        float s2 = wred(v0*v0+v1*v1+v2*v2+v3*v3);
        float mu = s * (1.f/128.f);
        float var = s2 * (1.f/128.f) - mu*mu;
        float rs = rsqrtf(var + 1e-5f);
        outstage[pp*OS_STRIDE + lane]      = (v0-mu)*rs*l2g[lane]    + l2b[lane];
        outstage[pp*OS_STRIDE + lane + 32] = (v1-mu)*rs*l2g[lane+32] + l2b[lane+32];
        outstage[pp*OS_STRIDE + lane + 64] = (v2-mu)*rs*l2g[lane+64] + l2b[lane+64];
        outstage[pp*OS_STRIDE + lane + 96] = (v3-mu)*rs*l2g[lane+96] + l2b[lane+96];
    }
    __syncthreads();

    // ---- transposed store ----
    for (int i = t; i < 64 * DDIM; i += 256) {
        int d = i >> 6, pp = i & 63;
        out[((size_t)b * DDIM + d) * PP + p0 + pp] = outstage[pp * OS_STRIDE + d];
    }
}

// ---------------------------------------------------------------------------
extern "C" void kernel_launch(void* const* d_in, const int* in_sizes, int n_in,
                              void* d_out, int out_size)
{
    const float* feature   = (const float*)d_in[0];
    const float* I_src     = (const float*)d_in[1];
    const float* I_tar_inv = (const float*)d_in[2];
    const float* E         = (const float*)d_in[3];
    const float* dis       = (const float*)d_in[4];
    const float* norm_vec  = (const float*)d_in[5];
    const float* bn_gamma  = (const float*)d_in[6];
    const float* bn_beta   = (const float*)d_in[7];
    const float* bn_mean   = (const float*)d_in[8];
    const float* bn_var    = (const float*)d_in[9];
    const float* conv_w    = (const float*)d_in[10];
    const float* ln1_g     = (const float*)d_in[11];
    const float* ln1_b     = (const float*)d_in[12];
    const float* mlp_w1    = (const float*)d_in[13];
    const float* mlp_b1    = (const float*)d_in[14];
    const float* mlp_w2    = (const float*)d_in[15];
    const float* mlp_b2    = (const float*)d_in[16];
    const float* ln2_g     = (const float*)d_in[17];
    const float* ln2_b     = (const float*)d_in[18];
    float* out = (float*)d_out;

    cudaFuncSetAttribute(k1_conv_tc,
                         cudaFuncAttributeMaxDynamicSharedMemorySize, K1_SMEM);
    cudaFuncSetAttribute(k3_mlp_tc,
                         cudaFuncAttributeMaxDynamicSharedMemorySize, K3T_SMEM);

    k0_prep<<<1, 256>>>(I_src, I_tar_inv, E, dis, norm_vec,
                        bn_gamma, bn_beta, bn_mean, bn_var);
    k0b_pack<<<64, 256>>>(conv_w, mlp_w1, mlp_w2);
    k1_conv_tc<<<dim3(PP/128, BN), 256, K1_SMEM>>>(feature);
    k2_attn<<<dim3(PP/8, BB), 256>>>();
    k3_mlp_tc<<<dim3(PP/64, BB), 256, K3T_SMEM>>>(ln1_g, ln1_b, mlp_b1, mlp_b2,
                                                  ln2_g, ln2_b, out);
}